// round 7
// baseline (speedup 1.0000x reference)
#include <cuda_runtime.h>
#include <cstdint>

#define NN 8192
#define DD 64
#define EE 16384
#define NEGV -1e10f
#define TINYF 1.17549435e-38f

#define NB 148
#define NT 256
#define TILE_J 128
#define TILE_STRIDE 68          // floats/row; 8-lane LDS.128 phases conflict-free
#define CAND_TILE 16

// ---------------- scratch ----------------
__device__ float g_queries[NN * DD];
__device__ float g_qn[NN];
__device__ float g_hn[NN];
__device__ int   g_gens0[NN];
__device__ int   g_glist[NN];
__device__ int   g_flag[NN];
__device__ unsigned long long g_best[NN];
__device__ int   g_newsend[NN];
__device__ int   g_newrec[NN];
__device__ int   g_ngens;
__device__ int   g_eactive;
__device__ int   g_ncand;

// grid barrier state (generation-based; survives graph replays)
__device__ int g_bar_count = 0;
__device__ volatile int g_bar_gen = 0;

__device__ __forceinline__ void grid_bar() {
  __syncthreads();
  if (threadIdx.x == 0) {
    int gen = g_bar_gen;
    __threadfence();
    if (atomicAdd(&g_bar_count, 1) == NB - 1) {
      g_bar_count = 0;
      __threadfence();
      g_bar_gen = gen + 1;
    } else {
      while (g_bar_gen == gen) { }
    }
    __threadfence();
  }
  __syncthreads();
}

// ---------------- threefry2x32 (JAX-exact) ----------------
__host__ __device__ __forceinline__ void threefry2x32(uint32_t k0, uint32_t k1,
                                                      uint32_t x0, uint32_t x1,
                                                      uint32_t* o0, uint32_t* o1) {
  uint32_t ks2 = k0 ^ k1 ^ 0x1BD11BDAu;
#define ROTL32(v, r) (((v) << (r)) | ((v) >> (32 - (r))))
#define TFRND(r) { x0 += x1; x1 = ROTL32(x1, r); x1 ^= x0; }
  x0 += k0; x1 += k1;
  TFRND(13) TFRND(15) TFRND(26) TFRND(6)
  x0 += k1; x1 += ks2 + 1u;
  TFRND(17) TFRND(29) TFRND(16) TFRND(24)
  x0 += ks2; x1 += k0 + 2u;
  TFRND(13) TFRND(15) TFRND(26) TFRND(6)
  x0 += k0; x1 += k1 + 3u;
  TFRND(17) TFRND(29) TFRND(16) TFRND(24)
  x0 += k1; x1 += ks2 + 4u;
  TFRND(13) TFRND(15) TFRND(26) TFRND(6)
  x0 += ks2; x1 += k0 + 5u;
  *o0 = x0; *o1 = x1;
#undef TFRND
#undef ROTL32
}

__device__ __forceinline__ uint32_t random_bits32(uint32_t k0, uint32_t k1,
                                                  unsigned long long idx) {
  uint32_t o0, o1;
  threefry2x32(k0, k1, (uint32_t)(idx >> 32), (uint32_t)idx, &o0, &o1);
  return o0 ^ o1;
}

__device__ __forceinline__ float u01_from_bits(uint32_t bits) {
  return __uint_as_float((bits >> 9) | 0x3f800000u) - 1.0f;
}

// XLA ErfInv (Giles)
__device__ __forceinline__ float xla_erfinv(float x) {
  float w = -log1pf(-x * x);
  float p;
  if (w < 5.f) {
    w -= 2.5f;
    p = 2.81022636e-08f;
    p = fmaf(p, w, 3.43273939e-07f);
    p = fmaf(p, w, -3.5233877e-06f);
    p = fmaf(p, w, -4.39150654e-06f);
    p = fmaf(p, w, 0.00021858087f);
    p = fmaf(p, w, -0.00125372503f);
    p = fmaf(p, w, -0.00417768164f);
    p = fmaf(p, w, 0.246640727f);
    p = fmaf(p, w, 1.50140941f);
  } else {
    w = sqrtf(w) - 3.f;
    p = -0.000200214257f;
    p = fmaf(p, w, 0.000100950558f);
    p = fmaf(p, w, 0.00134934322f);
    p = fmaf(p, w, -0.00367342844f);
    p = fmaf(p, w, 0.00573950773f);
    p = fmaf(p, w, -0.0076224613f);
    p = fmaf(p, w, 0.00943887047f);
    p = fmaf(p, w, 1.00167406f);
    p = fmaf(p, w, 2.83297682f);
  }
  return p * x;
}

__device__ __forceinline__ unsigned long long enc_key(float v, int j) {
  uint32_t u = __float_as_uint(v);
  u = (u & 0x80000000u) ? ~u : (u | 0x80000000u);
  return ((unsigned long long)u << 32) | (unsigned long long)(0xFFFFFFFFu - (uint32_t)j);
}

__device__ __forceinline__ int warp_incl_scan(int v, int lane) {
#pragma unroll
  for (int d = 1; d < 32; d <<= 1) {
    int o = __shfl_up_sync(0xffffffffu, v, d);
    if (lane >= d) v += o;
  }
  return v;
}

// full-logic output element writer (slow path)
__device__ __forceinline__ float4 out_full(int idx4, const float* __restrict__ edges,
                                           const int* __restrict__ senders,
                                           const int* __restrict__ receivers,
                                           int ea, int ngen, uint32_t ke0, uint32_t ke1) {
  const int T1 = EE * DD;
  int base = idx4 << 2;
  float4 v;
  if (base < T1) {
    v = reinterpret_cast<const float4*>(edges)[idx4];
    int e = base >> 6;
    if (e >= ea && e < ea + ngen) {
      float* vp = reinterpret_cast<float*>(&v);
#pragma unroll
      for (int cmp = 0; cmp < 4; cmp++) {
        uint32_t bits = random_bits32(ke0, ke1, (unsigned long long)(base + cmp));
        float u01 = u01_from_bits(bits);
        const float lo = -0.99999994f;
        float uu = fmaxf(lo, fmaf(u01, 2.0f, lo));
        vp[cmp] += 1.41421356f * xla_erfinv(uu);
      }
    }
  } else if (base < T1 + EE) {
    float* vp = reinterpret_cast<float*>(&v);
#pragma unroll
    for (int cmp = 0; cmp < 4; cmp++) {
      int j = base + cmp - T1;
      float x;
      if (j < ea)             x = (float)senders[j];
      else if (j < ea + ngen) x = (float)g_newsend[j - ea];
      else                    x = (float)(NN - 1);
      vp[cmp] = x;
    }
  } else if (base < T1 + 2 * EE) {
    float* vp = reinterpret_cast<float*>(&v);
#pragma unroll
    for (int cmp = 0; cmp < 4; cmp++) {
      int j = base + cmp - T1 - EE;
      float x;
      if (j < ea)             x = (float)receivers[j];
      else if (j < ea + ngen) x = (float)g_newrec[j - ea];
      else                    x = (float)(NN - 1);
      vp[cmp] = x;
    }
  } else {
    float* vp = reinterpret_cast<float*>(&v);
#pragma unroll
    for (int cmp = 0; cmp < 4; cmp++) {
      int j = base + cmp - T1 - 2 * EE;
      vp[cmp] = (j < ea + ngen) ? 1.0f : 0.0f;
    }
  }
  return v;
}

// =================== fused persistent kernel v2 ===================
__global__ void __launch_bounds__(NT, 1)
k_fused(const float* __restrict__ nodes, const float* __restrict__ edges,
        const int* __restrict__ receivers, const int* __restrict__ senders,
        const float* __restrict__ active_nodes, const float* __restrict__ active_edges,
        const float* __restrict__ Wq, const float* __restrict__ bq,
        const float* __restrict__ Wp, const float* __restrict__ bp,
        float* __restrict__ out, int out_size,
        uint32_t kp0, uint32_t kp1, uint32_t ke0, uint32_t ke1,
        uint32_t ks0, uint32_t ks1) {
  __shared__ __align__(16) float sh[TILE_J * TILE_STRIDE];   // 34816 B, phase-aliased
  __shared__ __align__(16) float qsh[CAND_TILE * DD];        // 4096 B
  __shared__ float s_qn[CAND_TILE];
  __shared__ int   s_ii[CAND_TILE];
  __shared__ int   swA[8];
  __shared__ int   swB[9];

  const int tid = threadIdx.x;
  const int lane = tid & 31;
  const int wid = tid >> 5;          // 0..7
  const int bid = blockIdx.x;

  // ---------------- Phase 0: prep (blocks 0..127) + e_active (block 128) ----------------
  if (bid < 128) {
    float* sWq = sh;                 // 4096 floats
    float* sbq = qsh;
    float* sWp = qsh + 64;
    {
      const float4* w4 = reinterpret_cast<const float4*>(Wq);
      float4* s4 = reinterpret_cast<float4*>(sWq);
#pragma unroll
      for (int r = 0; r < 4; r++) s4[tid + (r << 8)] = w4[tid + (r << 8)];
      if (tid < DD) { sbq[tid] = bq[tid]; sWp[tid] = Wp[tid]; }
    }
    __syncthreads();
    const float bp0 = bp[0];
#pragma unroll
    for (int r = 0; r < 8; r++) {
      const int i = (bid << 6) + (wid << 3) + r;
      float2 n2 = reinterpret_cast<const float2*>(nodes + i * DD)[lane];
      float2 b2 = reinterpret_cast<const float2*>(sbq)[lane];
      float q0 = b2.x, q1 = b2.y;
#pragma unroll
      for (int k = 0; k < DD; k++) {
        float nk = __shfl_sync(0xffffffffu, (k & 1) ? n2.y : n2.x, k >> 1);
        float2 w = reinterpret_cast<const float2*>(sWq + k * DD)[lane];
        q0 = fmaf(nk, w.x, q0);
        q1 = fmaf(nk, w.y, q1);
      }
      reinterpret_cast<float2*>(g_queries + i * DD)[lane] = make_float2(q0, q1);
      float2 wp2 = reinterpret_cast<const float2*>(sWp)[lane];
      float rq = q0 * q0 + q1 * q1;
      float rh = n2.x * n2.x + n2.y * n2.y;
      float rp = n2.x * wp2.x + n2.y * wp2.y;
#pragma unroll
      for (int d = 16; d > 0; d >>= 1) {
        rq += __shfl_xor_sync(0xffffffffu, rq, d);
        rh += __shfl_xor_sync(0xffffffffu, rh, d);
        rp += __shfl_xor_sync(0xffffffffu, rp, d);
      }
      if (lane == 0) {
        g_qn[i] = rq;
        g_hn[i] = rh;
        float z = rp + bp0;
        float prob = 0.5f * tanhf(0.5f * z) + 0.5f;   // XLA logistic
        uint32_t bits = random_bits32(kp0, kp1, (unsigned long long)i);
        float u = u01_from_bits(bits);
        g_gens0[i] = (u < prob * active_nodes[i]) ? 1 : 0;
        g_best[i] = 0ull;
      }
    }
  } else if (bid == 128) {
    // e_active reduction
    const float4* ae4 = reinterpret_cast<const float4*>(active_edges);
    float s = 0.f;
#pragma unroll
    for (int r = 0; r < 16; r++) {
      float4 v = ae4[tid + (r << 8)];
      s += v.x + v.y + v.z + v.w;
    }
#pragma unroll
    for (int d = 16; d > 0; d >>= 1) s += __shfl_xor_sync(0xffffffffu, s, d);
    __shared__ float swF[8];
    if (lane == 0) swF[wid] = s;
    __syncthreads();
    if (tid == 0) {
      float t = 0.f;
#pragma unroll
      for (int w = 0; w < 8; w++) t += swF[w];
      g_eactive = (int)t;
    }
  }
  grid_bar();

  // ---------------- Phase 1: listgen (block 0) ----------------
  if (bid == 0) {
    uint32_t fm = 0;
    const int4* g4 = reinterpret_cast<const int4*>(g_gens0 + tid * 32);
#pragma unroll
    for (int r = 0; r < 8; r++) {
      int4 v = g4[r];
      fm |= (uint32_t)v.x << (r * 4);
      fm |= (uint32_t)v.y << (r * 4 + 1);
      fm |= (uint32_t)v.z << (r * 4 + 2);
      fm |= (uint32_t)v.w << (r * 4 + 3);
    }
    int cnt = __popc(fm);
    int incl = warp_incl_scan(cnt, lane);
    if (lane == 31) swA[wid] = incl;
    __syncthreads();
    if (tid == 0) {
      swB[0] = 0;
#pragma unroll
      for (int w = 0; w < 8; w++) swB[w + 1] = swB[w] + swA[w];
      g_ncand = swB[8];
    }
    __syncthreads();
    int off = swB[wid] + incl - cnt;
#pragma unroll
    for (int r = 0; r < 32; r++) {
      if ((fm >> r) & 1u) {
        g_glist[off] = tid * 32 + r;
        g_flag[off] = 1;
        off++;
      }
    }
  }
  grid_bar();

  // ---------------- Phase 2: select (row-in-registers scoring) ----------------
  {
    const int jj = tid & 127;
    const int grp2 = tid >> 7;               // 0 or 1 -> cands [0,8) / [8,16)
    const int ncand = g_ncand;
    const int ng = (ncand + CAND_TILE - 1) >> 4;
    const int total = (NN / TILE_J) * ng;    // 64 * ng
    for (int w = bid; w < total; w += NB) {
      const int jb = w / ng;
      const int grp = w - jb * ng;
      const int c0 = grp << 4;
      const int jbase = jb << 7;
      // coalesced tile fill: 2048 float4
      {
        const float4* src = reinterpret_cast<const float4*>(nodes + (jbase << 6));
#pragma unroll
        for (int s = 0; s < 8; s++) {
          int idx4 = (s << 8) + tid;
          int row = idx4 >> 4, col4 = idx4 & 15;
          reinterpret_cast<float4*>(sh + row * TILE_STRIDE)[col4] = src[idx4];
        }
      }
      // qsh fill: 16 cands x 16 float4 = 256, one per thread
      {
        int c = tid >> 4, k4 = tid & 15;
        int idx = c0 + c;
        float4 qv = (idx < ncand)
            ? reinterpret_cast<const float4*>(g_queries + g_glist[idx] * DD)[k4]
            : make_float4(0.f, 0.f, 0.f, 0.f);
        reinterpret_cast<float4*>(qsh + c * DD)[k4] = qv;
      }
      if (tid < CAND_TILE) {
        int idx = c0 + tid;
        int i = (idx < ncand) ? g_glist[idx] : 0;
        s_ii[tid] = i;
        s_qn[tid] = g_qn[i];
      }
      __syncthreads();
      const int j = jbase + jj;
      const float hn = g_hn[j];
      const float act = active_nodes[j];
      // copy this thread's row into registers (one-time crossbar cost)
      float4 r4[16];
      {
        const float4* rowf4 = reinterpret_cast<const float4*>(sh + jj * TILE_STRIDE);
#pragma unroll
        for (int kk = 0; kk < 16; kk++) r4[kk] = rowf4[kk];
      }
      const int clim = (ncand - c0 < CAND_TILE) ? (ncand - c0) : CAND_TILE;
      const int cbeg = grp2 << 3;
      const int cend = (cbeg + 8 < clim) ? cbeg + 8 : clim;
      for (int c = cbeg; c < cend; c++) {
        const int i = s_ii[c];
        const float4* qf4 = reinterpret_cast<const float4*>(qsh + c * DD);
        float ax = 0.f, ay = 0.f, az = 0.f, aw = 0.f;
#pragma unroll
        for (int kk = 0; kk < 16; kk++) {
          float4 q = qf4[kk];
          ax = fmaf(q.x, r4[kk].x, ax);
          ay = fmaf(q.y, r4[kk].y, ay);
          az = fmaf(q.z, r4[kk].z, az);
          aw = fmaf(q.w, r4[kk].w, aw);
        }
        float num = (ax + az) + (ay + aw);
        float sc = num / (sqrtf(s_qn[c] * hn) + 1e-8f);
        sc = fminf(fmaxf(sc, -10000.f), 10000.f);
        if (act <= 0.f) sc = NEGV;
        if (j == i) sc = NEGV;
        unsigned long long lin = (unsigned long long)i * NN + (unsigned long long)j;
        uint32_t bits = random_bits32(ks0, ks1, lin);
        float u = fmaxf(TINYF, u01_from_bits(bits) + TINYF);
        float g = -logf(-logf(u));
        unsigned long long key = enc_key(sc + g, j);
#pragma unroll
        for (int d = 16; d > 0; d >>= 1) {
          unsigned long long o = __shfl_xor_sync(0xffffffffu, key, d);
          if (o > key) key = o;
        }
        if (lane == 0) atomicMax(&g_best[i], key);
      }
      __syncthreads();
    }
  }
  grid_bar();

  // ---------------- Phase 3: exist check (blocks 0..63, 1 edge/thread) ----------------
  if (bid < EE / NT) {
    unsigned long long* keys = reinterpret_cast<unsigned long long*>(sh);  // cap 4096
    const int ncand = g_ncand;
    const int e = (bid << 8) + tid;
    const unsigned long long ekey =
        ((unsigned long long)(uint32_t)senders[e] << 32) | (uint32_t)receivers[e];
    for (int base = 0; base < ncand; base += 4096) {
      int m = ncand - base;
      if (m > 4096) m = 4096;
      for (int t = tid; t < m; t += NT) {
        int i = g_glist[base + t];
        unsigned long long b = g_best[i];
        uint32_t sel = 0xFFFFFFFFu - (uint32_t)(b & 0xFFFFFFFFull);
        keys[t] = ((unsigned long long)(uint32_t)i << 32) | sel;
      }
      __syncthreads();
      for (int k = 0; k < m; k++) {
        if (ekey == keys[k]) g_flag[base + k] = 0;
      }
      __syncthreads();
    }
  }
  grid_bar();

  // ---------------- Phase 4: compact (block 0) ----------------
  if (bid == 0) {
    const int ncand = g_ncand;
    uint32_t fm = 0;
#pragma unroll
    for (int r = 0; r < 32; r++) {
      int c = tid * 32 + r;
      int f = (c < ncand) ? g_flag[c] : 0;
      fm |= (uint32_t)f << r;
    }
    int cnt = __popc(fm);
    int incl = warp_incl_scan(cnt, lane);
    if (lane == 31) swA[wid] = incl;
    __syncthreads();
    if (tid == 0) {
      swB[0] = 0;
#pragma unroll
      for (int w = 0; w < 8; w++) swB[w + 1] = swB[w] + swA[w];
      int total = swB[8];
      int allowed = EE - g_eactive - 1;
      int n = total < 0 ? 0 : total;
      if (n > allowed) n = allowed;
      g_ngens = n;
    }
    __syncthreads();
    int off = swB[wid] + incl - cnt;
#pragma unroll
    for (int r = 0; r < 32; r++) {
      if ((fm >> r) & 1u) {
        int c = tid * 32 + r;
        int i = g_glist[c];
        unsigned long long b = g_best[i];
        g_newsend[off] = i;
        g_newrec[off] = (int)(0xFFFFFFFFu - (uint32_t)(b & 0xFFFFFFFFull));
        off++;
      }
    }
  }
  grid_bar();

  // ---------------- Phase 5: output writer (MLP=4, copy fast path) ----------------
  {
    const int ngen = g_ngens;
    const int ea = g_eactive;
    const int T1 = EE * DD;
    const int n4 = out_size >> 2;
    const int S = NB * NT;
    float4* out4 = reinterpret_cast<float4*>(out);
    const float4* in4 = reinterpret_cast<const float4*>(edges);
    const int gtid = bid * NT + tid;
    int it = gtid;
    for (; it + 3 * S < n4; it += 4 * S) {
      const int i0 = it, i1 = it + S, i2 = it + 2 * S, i3 = it + 3 * S;
      // fast path: all four in edges region and none masked
      bool fast = ((i3 << 2) + 3) < T1;
      if (fast) {
        int e0 = i0 >> 4, e1 = i1 >> 4, e2 = i2 >> 4, e3 = i3 >> 4;
        fast = !((e0 >= ea && e0 < ea + ngen) || (e1 >= ea && e1 < ea + ngen) ||
                 (e2 >= ea && e2 < ea + ngen) || (e3 >= ea && e3 < ea + ngen));
      }
      if (fast) {
        float4 v0 = in4[i0], v1 = in4[i1], v2 = in4[i2], v3 = in4[i3];
        out4[i0] = v0; out4[i1] = v1; out4[i2] = v2; out4[i3] = v3;
      } else {
        out4[i0] = out_full(i0, edges, senders, receivers, ea, ngen, ke0, ke1);
        out4[i1] = out_full(i1, edges, senders, receivers, ea, ngen, ke0, ke1);
        out4[i2] = out_full(i2, edges, senders, receivers, ea, ngen, ke0, ke1);
        out4[i3] = out_full(i3, edges, senders, receivers, ea, ngen, ke0, ke1);
      }
    }
    for (; it < n4; it += S)
      out4[it] = out_full(it, edges, senders, receivers, ea, ngen, ke0, ke1);
    // scalar tail (out_size % 4 != 0 — not expected)
    for (int idx = (n4 << 2) + gtid; idx < out_size; idx += S) {
      float x = 0.f;
      if (idx < T1) {
        x = edges[idx];
        int e = idx >> 6;
        if (e >= ea && e < ea + ngen) {
          uint32_t bits = random_bits32(ke0, ke1, (unsigned long long)idx);
          float u01 = u01_from_bits(bits);
          const float lo = -0.99999994f;
          float u = fmaxf(lo, fmaf(u01, 2.0f, lo));
          x += 1.41421356f * xla_erfinv(u);
        }
      } else if (idx < T1 + EE) {
        int j = idx - T1;
        if (j < ea)             x = (float)senders[j];
        else if (j < ea + ngen) x = (float)g_newsend[j - ea];
        else                    x = (float)(NN - 1);
      } else if (idx < T1 + 2 * EE) {
        int j = idx - T1 - EE;
        if (j < ea)             x = (float)receivers[j];
        else if (j < ea + ngen) x = (float)g_newrec[j - ea];
        else                    x = (float)(NN - 1);
      } else if (idx < T1 + 3 * EE) {
        int j = idx - T1 - 2 * EE;
        x = (j < ea + ngen) ? 1.0f : 0.0f;
      }
      out[idx] = x;
    }
  }
}

// ---------------- host ----------------
extern "C" void kernel_launch(void* const* d_in, const int* in_sizes, int n_in,
                              void* d_out, int out_size) {
  const float* nodes        = (const float*)d_in[0];
  const float* edges        = (const float*)d_in[1];
  const int*   receivers    = (const int*)d_in[2];
  const int*   senders      = (const int*)d_in[3];
  const float* active_nodes = (const float*)d_in[4];
  const float* active_edges = (const float*)d_in[5];
  const float* Wq           = (const float*)d_in[6];
  const float* bq           = (const float*)d_in[7];
  const float* Wp           = (const float*)d_in[8];
  const float* bp           = (const float*)d_in[9];
  (void)in_sizes; (void)n_in;

  const uint32_t K0 = 0u, K1 = 42u;
  uint32_t kp0, kp1, ke0, ke1, ks0, ks1;
  threefry2x32(K0, K1, 0u, 0u, &kp0, &kp1);  // key_prob
  threefry2x32(K0, K1, 0u, 1u, &ke0, &ke1);  // key_edges
  threefry2x32(K0, K1, 0u, 2u, &ks0, &ks1);  // key_samp

  k_fused<<<NB, NT>>>(nodes, edges, receivers, senders, active_nodes, active_edges,
                      Wq, bq, Wp, bp, (float*)d_out, out_size,
                      kp0, kp1, ke0, ke1, ks0, ks1);
}

// round 8
// speedup vs baseline: 1.4408x; 1.4408x over previous
#include <cuda_runtime.h>
#include <cstdint>

#define NN 8192
#define DD 64
#define EE 16384
#define NEGV -1e10f
#define TINYF 1.17549435e-38f

#define NBP 512              // prep blocks (512 x 512thr, 1 node/warp)
#define NBS 296              // select blocks
#define SEL_THREADS 256
#define TILE_J 128
#define TILE_STRIDE 68
#define NCHUNK (NN / TILE_J)
#define CAND_TILE 32
#define HASH_SZ 2048
#define HASH_CAP 1536
#define EMPTYK 0xFFFFFFFFFFFFFFFFull

// ---------------- scratch ----------------
__device__ float g_queries[NN * DD];
__device__ float g_qn[NN];
__device__ float g_hn[NN];
__device__ int   g_gens0[NN];
__device__ int   g_glist[NN];
__device__ int   g_flag[NN];
__device__ unsigned long long g_best[NN];
__device__ int   g_newsend[NN];
__device__ int   g_newrec[NN];
__device__ int   g_ngens;
__device__ int   g_eactive;
__device__ int   g_ncand;
__device__ int   g_done_prep = 0;
__device__ int   g_done_sel = 0;

// ---------------- threefry2x32 (JAX-exact) ----------------
__host__ __device__ __forceinline__ void threefry2x32(uint32_t k0, uint32_t k1,
                                                      uint32_t x0, uint32_t x1,
                                                      uint32_t* o0, uint32_t* o1) {
  uint32_t ks2 = k0 ^ k1 ^ 0x1BD11BDAu;
#define ROTL32(v, r) (((v) << (r)) | ((v) >> (32 - (r))))
#define TFRND(r) { x0 += x1; x1 = ROTL32(x1, r); x1 ^= x0; }
  x0 += k0; x1 += k1;
  TFRND(13) TFRND(15) TFRND(26) TFRND(6)
  x0 += k1; x1 += ks2 + 1u;
  TFRND(17) TFRND(29) TFRND(16) TFRND(24)
  x0 += ks2; x1 += k0 + 2u;
  TFRND(13) TFRND(15) TFRND(26) TFRND(6)
  x0 += k0; x1 += k1 + 3u;
  TFRND(17) TFRND(29) TFRND(16) TFRND(24)
  x0 += k1; x1 += ks2 + 4u;
  TFRND(13) TFRND(15) TFRND(26) TFRND(6)
  x0 += ks2; x1 += k0 + 5u;
  *o0 = x0; *o1 = x1;
#undef TFRND
#undef ROTL32
}

__device__ __forceinline__ uint32_t random_bits32(uint32_t k0, uint32_t k1,
                                                  unsigned long long idx) {
  uint32_t o0, o1;
  threefry2x32(k0, k1, (uint32_t)(idx >> 32), (uint32_t)idx, &o0, &o1);
  return o0 ^ o1;
}

__device__ __forceinline__ float u01_from_bits(uint32_t bits) {
  return __uint_as_float((bits >> 9) | 0x3f800000u) - 1.0f;
}

// XLA ErfInv (Giles)
__device__ __forceinline__ float xla_erfinv(float x) {
  float w = -log1pf(-x * x);
  float p;
  if (w < 5.f) {
    w -= 2.5f;
    p = 2.81022636e-08f;
    p = fmaf(p, w, 3.43273939e-07f);
    p = fmaf(p, w, -3.5233877e-06f);
    p = fmaf(p, w, -4.39150654e-06f);
    p = fmaf(p, w, 0.00021858087f);
    p = fmaf(p, w, -0.00125372503f);
    p = fmaf(p, w, -0.00417768164f);
    p = fmaf(p, w, 0.246640727f);
    p = fmaf(p, w, 1.50140941f);
  } else {
    w = sqrtf(w) - 3.f;
    p = -0.000200214257f;
    p = fmaf(p, w, 0.000100950558f);
    p = fmaf(p, w, 0.00134934322f);
    p = fmaf(p, w, -0.00367342844f);
    p = fmaf(p, w, 0.00573950773f);
    p = fmaf(p, w, -0.0076224613f);
    p = fmaf(p, w, 0.00943887047f);
    p = fmaf(p, w, 1.00167406f);
    p = fmaf(p, w, 2.83297682f);
  }
  return p * x;
}

__device__ __forceinline__ unsigned long long enc_key(float v, int j) {
  uint32_t u = __float_as_uint(v);
  u = (u & 0x80000000u) ? ~u : (u | 0x80000000u);
  return ((unsigned long long)u << 32) | (unsigned long long)(0xFFFFFFFFu - (uint32_t)j);
}

__device__ __forceinline__ int warp_incl_scan(int v, int lane) {
#pragma unroll
  for (int d = 1; d < 32; d <<= 1) {
    int o = __shfl_up_sync(0xffffffffu, v, d);
    if (lane >= d) v += o;
  }
  return v;
}

// ============ Kernel 1: prep (1 node/warp) + last-block listgen ============
__global__ void __launch_bounds__(512) k_prep(const float* __restrict__ nodes,
                                              const float* __restrict__ Wq,
                                              const float* __restrict__ bq,
                                              const float* __restrict__ Wp,
                                              const float* __restrict__ bp,
                                              const float* __restrict__ active_nodes,
                                              const float* __restrict__ active_edges,
                                              uint32_t kp0, uint32_t kp1) {
  __shared__ __align__(16) float sWq[DD * DD];
  __shared__ float sbq[DD];
  __shared__ float sWp[DD];
  __shared__ int   s_last;
  __shared__ int   swA[16];
  __shared__ int   swB[17];
  __shared__ float swF[16];
  const int tid = threadIdx.x;
  const int warp = tid >> 5, lane = tid & 31;
  {
    const float4* w4 = reinterpret_cast<const float4*>(Wq);
    float4* s4 = reinterpret_cast<float4*>(sWq);
#pragma unroll
    for (int r = 0; r < 2; r++) s4[tid + (r << 9)] = w4[tid + (r << 9)];
    if (tid < DD) { sbq[tid] = bq[tid]; sWp[tid] = Wp[tid]; }
  }
  __syncthreads();
  const int i = (blockIdx.x << 4) + warp;
  float2 n2 = reinterpret_cast<const float2*>(nodes + i * DD)[lane];
  float2 b2 = reinterpret_cast<const float2*>(sbq)[lane];
  float q0 = b2.x, q1 = b2.y;
#pragma unroll
  for (int k = 0; k < DD; k++) {
    float nk = __shfl_sync(0xffffffffu, (k & 1) ? n2.y : n2.x, k >> 1);
    float2 w = reinterpret_cast<const float2*>(sWq + k * DD)[lane];
    q0 = fmaf(nk, w.x, q0);
    q1 = fmaf(nk, w.y, q1);
  }
  reinterpret_cast<float2*>(g_queries + i * DD)[lane] = make_float2(q0, q1);
  float2 wp2 = reinterpret_cast<const float2*>(sWp)[lane];
  float rq = q0 * q0 + q1 * q1;
  float rh = n2.x * n2.x + n2.y * n2.y;
  float rp = n2.x * wp2.x + n2.y * wp2.y;
#pragma unroll
  for (int d = 16; d > 0; d >>= 1) {
    rq += __shfl_xor_sync(0xffffffffu, rq, d);
    rh += __shfl_xor_sync(0xffffffffu, rh, d);
    rp += __shfl_xor_sync(0xffffffffu, rp, d);
  }
  if (lane == 0) {
    g_qn[i] = rq;
    g_hn[i] = rh;
    float z = rp + bp[0];
    float prob = 0.5f * tanhf(0.5f * z) + 0.5f;   // XLA logistic
    uint32_t bits = random_bits32(kp0, kp1, (unsigned long long)i);
    float u = u01_from_bits(bits);
    g_gens0[i] = (u < prob * active_nodes[i]) ? 1 : 0;
    g_best[i] = 0ull;
  }
  // ------- last-block tail: e_active + ordered compaction -------
  __syncthreads();
  if (tid == 0) {
    __threadfence();
    int prev = atomicAdd(&g_done_prep, 1);
    s_last = (prev == NBP - 1) ? 1 : 0;
    if (s_last) g_done_prep = 0;           // reset for next graph replay
  }
  __syncthreads();
  if (!s_last) return;

  // e_active sum: 16384 floats, 512 threads -> 8 float4 each
  {
    const float4* ae4 = reinterpret_cast<const float4*>(active_edges);
    float s = 0.f;
#pragma unroll
    for (int r = 0; r < 8; r++) {
      float4 v = ae4[tid + (r << 9)];
      s += v.x + v.y + v.z + v.w;
    }
#pragma unroll
    for (int d = 16; d > 0; d >>= 1) s += __shfl_xor_sync(0xffffffffu, s, d);
    if (lane == 0) swF[warp] = s;
  }
  // generator compaction: 16 flags/thread
  uint32_t fm = 0;
  {
    const int4* g4 = reinterpret_cast<const int4*>(g_gens0 + tid * 16);
#pragma unroll
    for (int r = 0; r < 4; r++) {
      int4 v = g4[r];
      fm |= (uint32_t)v.x << (r * 4);
      fm |= (uint32_t)v.y << (r * 4 + 1);
      fm |= (uint32_t)v.z << (r * 4 + 2);
      fm |= (uint32_t)v.w << (r * 4 + 3);
    }
  }
  int cnt = __popc(fm);
  int incl = warp_incl_scan(cnt, lane);
  if (lane == 31) swA[warp] = incl;
  __syncthreads();
  if (tid == 0) {
    swB[0] = 0;
#pragma unroll
    for (int w = 0; w < 16; w++) swB[w + 1] = swB[w] + swA[w];
    g_ncand = swB[16];
    float t = 0.f;
#pragma unroll
    for (int w = 0; w < 16; w++) t += swF[w];
    g_eactive = (int)t;
  }
  __syncthreads();
  int off = swB[warp] + incl - cnt;
#pragma unroll
  for (int r = 0; r < 16; r++) {
    if ((fm >> r) & 1u) {
      g_glist[off] = tid * 16 + r;
      g_flag[off] = 1;
      off++;
    }
  }
}

// ===== Kernel 2: select (R4 body) + last-block tail (hash exist + compact) =====
__global__ void __launch_bounds__(SEL_THREADS) k_select(const float* __restrict__ nodes,
                                                        const float* __restrict__ active_nodes,
                                                        const int* __restrict__ senders,
                                                        const int* __restrict__ receivers,
                                                        uint32_t ks0, uint32_t ks1) {
  __shared__ __align__(16) float sh[TILE_J * TILE_STRIDE];
  __shared__ __align__(16) float qsh[CAND_TILE * DD];
  __shared__ float s_qn[CAND_TILE];
  __shared__ int   s_ii[CAND_TILE];
  __shared__ int   s_last;
  __shared__ int   swA[8];
  __shared__ int   swB[9];
  const int tid = threadIdx.x;
  const int lane = tid & 31;
  const int wid = tid >> 5;
  const int jj = tid & 127;
  const int grp2 = tid >> 7;
  const int ncand = g_ncand;
  const int ng = (ncand + CAND_TILE - 1) / CAND_TILE;
  const int total = NCHUNK * ng;
  for (int w = blockIdx.x; w < total; w += NBS) {
    const int chunk = w / ng;
    const int grp = w - chunk * ng;
    const int c0 = grp * CAND_TILE;
    const int jbase = chunk << 7;
    {
      const float4* src = reinterpret_cast<const float4*>(nodes + (jbase << 6));
#pragma unroll
      for (int s = 0; s < 8; s++) {
        int idx4 = (s << 8) + tid;
        int row = idx4 >> 4, col4 = idx4 & 15;
        reinterpret_cast<float4*>(sh + row * TILE_STRIDE)[col4] = src[idx4];
      }
    }
    if (tid < CAND_TILE) {
      int idx = c0 + tid;
      int i = (idx < ncand) ? g_glist[idx] : 0;
      s_ii[tid] = i;
      s_qn[tid] = g_qn[i];
    }
#pragma unroll
    for (int s = 0; s < 2; s++) {
      int t4 = (s << 8) + tid;
      int c = t4 >> 4, k4 = t4 & 15;
      int idx = c0 + c;
      float4 qv = (idx < ncand)
          ? reinterpret_cast<const float4*>(g_queries + g_glist[idx] * DD)[k4]
          : make_float4(0.f, 0.f, 0.f, 0.f);
      reinterpret_cast<float4*>(qsh + c * DD)[k4] = qv;
    }
    __syncthreads();
    const int j = jbase + jj;
    const float hn = g_hn[j];
    const float act = active_nodes[j];
    const float4* rowf4 = reinterpret_cast<const float4*>(sh + jj * TILE_STRIDE);
    const int clim = (ncand - c0 < CAND_TILE) ? (ncand - c0) : CAND_TILE;
    const int cbeg = grp2 << 4;
    const int cend = (cbeg + 16 < clim) ? cbeg + 16 : clim;
    for (int c = cbeg; c < cend; c++) {
      const int i = s_ii[c];
      const float4* qf4 = reinterpret_cast<const float4*>(qsh + c * DD);
      float ax = 0.f, ay = 0.f, az = 0.f, aw = 0.f;
#pragma unroll
      for (int kk = 0; kk < 16; kk++) {
        float4 r = rowf4[kk];
        float4 q = qf4[kk];
        ax = fmaf(q.x, r.x, ax);
        ay = fmaf(q.y, r.y, ay);
        az = fmaf(q.z, r.z, az);
        aw = fmaf(q.w, r.w, aw);
      }
      float num = (ax + az) + (ay + aw);
      float sc = num / (sqrtf(s_qn[c] * hn) + 1e-8f);
      sc = fminf(fmaxf(sc, -10000.f), 10000.f);
      if (act <= 0.f) sc = NEGV;
      if (j == i) sc = NEGV;
      unsigned long long lin = (unsigned long long)i * NN + (unsigned long long)j;
      uint32_t bits = random_bits32(ks0, ks1, lin);
      float u = fmaxf(TINYF, u01_from_bits(bits) + TINYF);
      float g = -logf(-logf(u));
      unsigned long long key = enc_key(sc + g, j);
#pragma unroll
      for (int d = 16; d > 0; d >>= 1) {
        unsigned long long o = __shfl_xor_sync(0xffffffffu, key, d);
        if (o > key) key = o;
      }
      if (lane == 0) atomicMax(&g_best[i], key);
    }
    __syncthreads();
  }
  // ------- last-block tail: hash-based exist check + compaction -------
  if (tid == 0) {
    __threadfence();
    int prev = atomicAdd(&g_done_sel, 1);
    s_last = (prev == NBS - 1) ? 1 : 0;
    if (s_last) g_done_sel = 0;
  }
  __syncthreads();
  if (!s_last) return;

  unsigned long long* hkey = reinterpret_cast<unsigned long long*>(sh);  // 2048 * 8B
  int* hcid = reinterpret_cast<int*>(sh) + 4096;                         // 2048 * 4B

  if (ncand <= HASH_CAP) {
    // build hash of (i, sel)
#pragma unroll
    for (int r = 0; r < HASH_SZ / SEL_THREADS; r++) hkey[tid + r * SEL_THREADS] = EMPTYK;
    __syncthreads();
    for (int c = tid; c < ncand; c += SEL_THREADS) {
      int i = g_glist[c];
      unsigned long long b = g_best[i];
      uint32_t sel = 0xFFFFFFFFu - (uint32_t)(b & 0xFFFFFFFFull);
      unsigned long long key = ((unsigned long long)(uint32_t)i << 32) | sel;
      uint32_t h = (uint32_t)((key * 0x9E3779B97F4A7C15ull) >> 40) & (HASH_SZ - 1);
      while (true) {
        unsigned long long prev = atomicCAS(&hkey[h], EMPTYK, key);
        if (prev == EMPTYK) { hcid[h] = c; break; }
        h = (h + 1) & (HASH_SZ - 1);
      }
    }
    __syncthreads();
    // scan all edges, probe
    const int4* s4 = reinterpret_cast<const int4*>(senders);
    const int4* r4 = reinterpret_cast<const int4*>(receivers);
#pragma unroll
    for (int r = 0; r < EE / 4 / SEL_THREADS; r++) {       // 16 iters
      int idx4 = tid + r * SEL_THREADS;
      int4 sv = s4[idx4];
      int4 rv = r4[idx4];
      const int ss[4] = {sv.x, sv.y, sv.z, sv.w};
      const int rr[4] = {rv.x, rv.y, rv.z, rv.w};
#pragma unroll
      for (int q = 0; q < 4; q++) {
        unsigned long long key =
            ((unsigned long long)(uint32_t)ss[q] << 32) | (uint32_t)rr[q];
        uint32_t h = (uint32_t)((key * 0x9E3779B97F4A7C15ull) >> 40) & (HASH_SZ - 1);
        while (true) {
          unsigned long long k = hkey[h];
          if (k == EMPTYK) break;
          if (k == key) { g_flag[hcid[h]] = 0; break; }
          h = (h + 1) & (HASH_SZ - 1);
        }
      }
    }
    __syncthreads();
  } else {
    // fallback (never expected with this data): chunked smem compare
    for (int base = 0; base < ncand; base += HASH_SZ) {
      int m = ncand - base;
      if (m > HASH_SZ) m = HASH_SZ;
      for (int t = tid; t < m; t += SEL_THREADS) {
        int i = g_glist[base + t];
        unsigned long long b = g_best[i];
        uint32_t sel = 0xFFFFFFFFu - (uint32_t)(b & 0xFFFFFFFFull);
        hkey[t] = ((unsigned long long)(uint32_t)i << 32) | sel;
      }
      __syncthreads();
      for (int e = tid; e < EE; e += SEL_THREADS) {
        unsigned long long ekey =
            ((unsigned long long)(uint32_t)senders[e] << 32) | (uint32_t)receivers[e];
        for (int k = 0; k < m; k++)
          if (ekey == hkey[k]) g_flag[base + k] = 0;
      }
      __syncthreads();
    }
  }

  // compaction: 256 threads x 32 flags
  uint32_t fm = 0;
#pragma unroll
  for (int r = 0; r < 32; r++) {
    int c = tid * 32 + r;
    int f = (c < ncand) ? g_flag[c] : 0;
    fm |= (uint32_t)f << r;
  }
  int cnt = __popc(fm);
  int incl = warp_incl_scan(cnt, lane);
  if (lane == 31) swA[wid] = incl;
  __syncthreads();
  if (tid == 0) {
    swB[0] = 0;
#pragma unroll
    for (int w = 0; w < 8; w++) swB[w + 1] = swB[w] + swA[w];
    int tot = swB[8];
    int allowed = EE - g_eactive - 1;
    int n = tot < 0 ? 0 : tot;
    if (n > allowed) n = allowed;
    g_ngens = n;
  }
  __syncthreads();
  int off = swB[wid] + incl - cnt;
#pragma unroll
  for (int r = 0; r < 32; r++) {
    if ((fm >> r) & 1u) {
      int c = tid * 32 + r;
      int i = g_glist[c];
      unsigned long long b = g_best[i];
      g_newsend[off] = i;
      g_newrec[off] = (int)(0xFFFFFFFFu - (uint32_t)(b & 0xFFFFFFFFull));
      off++;
    }
  }
}

// ---------- Kernel 3: vectorized output writer (MLP=4) ----------
// Layout: [ new_edges (E*D f32) | nsend (E) | nrec (E) | naedges (E) ]
__global__ void k_out4(const float* __restrict__ edges, const int* __restrict__ senders,
                       const int* __restrict__ receivers, float4* __restrict__ out,
                       uint32_t ke0, uint32_t ke1, int n4) {
  const int ngen = g_ngens;
  const int ea = g_eactive;
  const int T1 = EE * DD;
  const int base0 = blockIdx.x * (blockDim.x << 2) + threadIdx.x;
#pragma unroll
  for (int u = 0; u < 4; u++) {
    int idx4 = base0 + u * blockDim.x;
    if (idx4 >= n4) continue;
    int base = idx4 << 2;
    float4 v;
    if (base < T1) {
      v = reinterpret_cast<const float4*>(edges)[idx4];
      int e = base >> 6;
      if (e >= ea && e < ea + ngen) {
        float* vp = reinterpret_cast<float*>(&v);
#pragma unroll
        for (int cmp = 0; cmp < 4; cmp++) {
          uint32_t bits = random_bits32(ke0, ke1, (unsigned long long)(base + cmp));
          float u01 = u01_from_bits(bits);
          const float lo = -0.99999994f;
          float uu = fmaxf(lo, fmaf(u01, 2.0f, lo));
          vp[cmp] += 1.41421356f * xla_erfinv(uu);
        }
      }
    } else if (base < T1 + EE) {
      float* vp = reinterpret_cast<float*>(&v);
#pragma unroll
      for (int cmp = 0; cmp < 4; cmp++) {
        int j = base + cmp - T1;
        float x;
        if (j < ea)             x = (float)senders[j];
        else if (j < ea + ngen) x = (float)g_newsend[j - ea];
        else                    x = (float)(NN - 1);
        vp[cmp] = x;
      }
    } else if (base < T1 + 2 * EE) {
      float* vp = reinterpret_cast<float*>(&v);
#pragma unroll
      for (int cmp = 0; cmp < 4; cmp++) {
        int j = base + cmp - T1 - EE;
        float x;
        if (j < ea)             x = (float)receivers[j];
        else if (j < ea + ngen) x = (float)g_newrec[j - ea];
        else                    x = (float)(NN - 1);
        vp[cmp] = x;
      }
    } else {
      float* vp = reinterpret_cast<float*>(&v);
#pragma unroll
      for (int cmp = 0; cmp < 4; cmp++) {
        int j = base + cmp - T1 - 2 * EE;
        vp[cmp] = (j < ea + ngen) ? 1.0f : 0.0f;
      }
    }
    out[idx4] = v;
  }
}

// fallback scalar writer (out_size % 4 != 0 — not expected)
__global__ void k_out1(const float* __restrict__ edges, const int* __restrict__ senders,
                       const int* __restrict__ receivers, float* __restrict__ out,
                       uint32_t ke0, uint32_t ke1, int start, int out_size) {
  int idx = start + blockIdx.x * blockDim.x + threadIdx.x;
  if (idx >= out_size) return;
  const int ngen = g_ngens;
  const int ea = g_eactive;
  const int T1 = EE * DD;
  float x = 0.f;
  if (idx < T1) {
    x = edges[idx];
    int e = idx >> 6;
    if (e >= ea && e < ea + ngen) {
      uint32_t bits = random_bits32(ke0, ke1, (unsigned long long)idx);
      float u01 = u01_from_bits(bits);
      const float lo = -0.99999994f;
      float u = fmaxf(lo, fmaf(u01, 2.0f, lo));
      x += 1.41421356f * xla_erfinv(u);
    }
  } else if (idx < T1 + EE) {
    int j = idx - T1;
    if (j < ea)             x = (float)senders[j];
    else if (j < ea + ngen) x = (float)g_newsend[j - ea];
    else                    x = (float)(NN - 1);
  } else if (idx < T1 + 2 * EE) {
    int j = idx - T1 - EE;
    if (j < ea)             x = (float)receivers[j];
    else if (j < ea + ngen) x = (float)g_newrec[j - ea];
    else                    x = (float)(NN - 1);
  } else if (idx < T1 + 3 * EE) {
    int j = idx - T1 - 2 * EE;
    x = (j < ea + ngen) ? 1.0f : 0.0f;
  }
  out[idx] = x;
}

// ---------------- host ----------------
extern "C" void kernel_launch(void* const* d_in, const int* in_sizes, int n_in,
                              void* d_out, int out_size) {
  const float* nodes        = (const float*)d_in[0];
  const float* edges        = (const float*)d_in[1];
  const int*   receivers    = (const int*)d_in[2];
  const int*   senders      = (const int*)d_in[3];
  const float* active_nodes = (const float*)d_in[4];
  const float* active_edges = (const float*)d_in[5];
  const float* Wq           = (const float*)d_in[6];
  const float* bq           = (const float*)d_in[7];
  const float* Wp           = (const float*)d_in[8];
  const float* bp           = (const float*)d_in[9];
  (void)in_sizes; (void)n_in;

  const uint32_t K0 = 0u, K1 = 42u;
  uint32_t kp0, kp1, ke0, ke1, ks0, ks1;
  threefry2x32(K0, K1, 0u, 0u, &kp0, &kp1);  // key_prob
  threefry2x32(K0, K1, 0u, 1u, &ke0, &ke1);  // key_edges
  threefry2x32(K0, K1, 0u, 2u, &ks0, &ks1);  // key_samp

  k_prep<<<NBP, 512>>>(nodes, Wq, bq, Wp, bp, active_nodes, active_edges, kp0, kp1);
  k_select<<<NBS, SEL_THREADS>>>(nodes, active_nodes, senders, receivers, ks0, ks1);

  int n4 = out_size >> 2;
  if (n4 > 0) {
    int blocks = (n4 + 1023) / 1024;
    k_out4<<<blocks, 256>>>(edges, senders, receivers, (float4*)d_out, ke0, ke1, n4);
  }
  int rem_start = n4 << 2;
  if (rem_start < out_size)
    k_out1<<<1, 256>>>(edges, senders, receivers, (float*)d_out, ke0, ke1,
                       rem_start, out_size);
}

// round 9
// speedup vs baseline: 2.1349x; 1.4817x over previous
#include <cuda_runtime.h>
#include <cstdint>

#define NN 8192
#define DD 64
#define EE 16384
#define NEGV -1e10f
#define TINYF 1.17549435e-38f

#define SEL_THREADS 256
#define TILE_J 128
#define TILE_STRIDE 68          // floats; 272B rows -> 16B aligned, LDS.128 conflict-free
#define NCHUNK (NN / TILE_J)    // 64
#define CAND_TILE 32
#define HASH_SZ 2048
#define HASH_CAP 1536
#define EMPTYK 0xFFFFFFFFFFFFFFFFull

// ---------------- scratch ----------------
__device__ float g_queries[NN * DD];
__device__ float g_qn[NN];
__device__ float g_hn[NN];
__device__ int   g_gens0[NN];
__device__ int   g_glist[NN];
__device__ int   g_flag[NN];
__device__ unsigned long long g_best[NN];
__device__ int   g_newsend[NN];
__device__ int   g_newrec[NN];
__device__ int   g_ngens;
__device__ int   g_eactive;
__device__ int   g_ncand;

// ---------------- threefry2x32 (JAX-exact) ----------------
__host__ __device__ __forceinline__ void threefry2x32(uint32_t k0, uint32_t k1,
                                                      uint32_t x0, uint32_t x1,
                                                      uint32_t* o0, uint32_t* o1) {
  uint32_t ks2 = k0 ^ k1 ^ 0x1BD11BDAu;
#define ROTL32(v, r) (((v) << (r)) | ((v) >> (32 - (r))))
#define TFRND(r) { x0 += x1; x1 = ROTL32(x1, r); x1 ^= x0; }
  x0 += k0; x1 += k1;
  TFRND(13) TFRND(15) TFRND(26) TFRND(6)
  x0 += k1; x1 += ks2 + 1u;
  TFRND(17) TFRND(29) TFRND(16) TFRND(24)
  x0 += ks2; x1 += k0 + 2u;
  TFRND(13) TFRND(15) TFRND(26) TFRND(6)
  x0 += k0; x1 += k1 + 3u;
  TFRND(17) TFRND(29) TFRND(16) TFRND(24)
  x0 += k1; x1 += ks2 + 4u;
  TFRND(13) TFRND(15) TFRND(26) TFRND(6)
  x0 += ks2; x1 += k0 + 5u;
  *o0 = x0; *o1 = x1;
#undef TFRND
#undef ROTL32
}

__device__ __forceinline__ uint32_t random_bits32(uint32_t k0, uint32_t k1,
                                                  unsigned long long idx) {
  uint32_t o0, o1;
  threefry2x32(k0, k1, (uint32_t)(idx >> 32), (uint32_t)idx, &o0, &o1);
  return o0 ^ o1;
}

__device__ __forceinline__ float u01_from_bits(uint32_t bits) {
  return __uint_as_float((bits >> 9) | 0x3f800000u) - 1.0f;
}

// XLA ErfInv (Giles)
__device__ __forceinline__ float xla_erfinv(float x) {
  float w = -log1pf(-x * x);
  float p;
  if (w < 5.f) {
    w -= 2.5f;
    p = 2.81022636e-08f;
    p = fmaf(p, w, 3.43273939e-07f);
    p = fmaf(p, w, -3.5233877e-06f);
    p = fmaf(p, w, -4.39150654e-06f);
    p = fmaf(p, w, 0.00021858087f);
    p = fmaf(p, w, -0.00125372503f);
    p = fmaf(p, w, -0.00417768164f);
    p = fmaf(p, w, 0.246640727f);
    p = fmaf(p, w, 1.50140941f);
  } else {
    w = sqrtf(w) - 3.f;
    p = -0.000200214257f;
    p = fmaf(p, w, 0.000100950558f);
    p = fmaf(p, w, 0.00134934322f);
    p = fmaf(p, w, -0.00367342844f);
    p = fmaf(p, w, 0.00573950773f);
    p = fmaf(p, w, -0.0076224613f);
    p = fmaf(p, w, 0.00943887047f);
    p = fmaf(p, w, 1.00167406f);
    p = fmaf(p, w, 2.83297682f);
  }
  return p * x;
}

__device__ __forceinline__ unsigned long long enc_key(float v, int j) {
  uint32_t u = __float_as_uint(v);
  u = (u & 0x80000000u) ? ~u : (u | 0x80000000u);
  return ((unsigned long long)u << 32) | (unsigned long long)(0xFFFFFFFFu - (uint32_t)j);
}

__device__ __forceinline__ int warp_incl_scan(int v, int lane) {
#pragma unroll
  for (int d = 1; d < 32; d <<= 1) {
    int o = __shfl_up_sync(0xffffffffu, v, d);
    if (lane >= d) v += o;
  }
  return v;
}

// ---------- Kernel A: prep — 128 blocks, Wq staged once, 4 nodes/warp ----------
__global__ void __launch_bounds__(512) k_prep(const float* __restrict__ nodes,
                                              const float* __restrict__ Wq,
                                              const float* __restrict__ bq,
                                              const float* __restrict__ Wp,
                                              const float* __restrict__ bp,
                                              const float* __restrict__ active_nodes,
                                              uint32_t kp0, uint32_t kp1) {
  __shared__ __align__(16) float sWq[DD * DD];
  __shared__ float sbq[DD];
  __shared__ float sWp[DD];
  const int tid = threadIdx.x;
  const int warp = tid >> 5, lane = tid & 31;
  {
    const float4* w4 = reinterpret_cast<const float4*>(Wq);
    float4* s4 = reinterpret_cast<float4*>(sWq);
#pragma unroll
    for (int r = 0; r < 2; r++) s4[tid + (r << 9)] = w4[tid + (r << 9)];
    if (tid < DD) { sbq[tid] = bq[tid]; sWp[tid] = Wp[tid]; }
  }
  const int ibase = (blockIdx.x << 6) + (warp << 2);
  // prefetch the 4 node rows (MLP=4) while Wq stages
  float2 n2r[4];
#pragma unroll
  for (int r = 0; r < 4; r++)
    n2r[r] = reinterpret_cast<const float2*>(nodes + (ibase + r) * DD)[lane];
  float anr[4];
#pragma unroll
  for (int r = 0; r < 4; r++) anr[r] = active_nodes[ibase + r];
  __syncthreads();
  const float2 b2 = reinterpret_cast<const float2*>(sbq)[lane];
  const float2 wp2 = reinterpret_cast<const float2*>(sWp)[lane];
  const float bp0 = bp[0];
#pragma unroll
  for (int r = 0; r < 4; r++) {
    const int i = ibase + r;
    const float2 n2 = n2r[r];
    float q0 = b2.x, q1 = b2.y;
#pragma unroll
    for (int k = 0; k < DD; k++) {
      float nk = __shfl_sync(0xffffffffu, (k & 1) ? n2.y : n2.x, k >> 1);
      float2 w = reinterpret_cast<const float2*>(sWq + k * DD)[lane];
      q0 = fmaf(nk, w.x, q0);
      q1 = fmaf(nk, w.y, q1);
    }
    reinterpret_cast<float2*>(g_queries + i * DD)[lane] = make_float2(q0, q1);
    float rq = q0 * q0 + q1 * q1;
    float rh = n2.x * n2.x + n2.y * n2.y;
    float rp = n2.x * wp2.x + n2.y * wp2.y;
#pragma unroll
    for (int d = 16; d > 0; d >>= 1) {
      rq += __shfl_xor_sync(0xffffffffu, rq, d);
      rh += __shfl_xor_sync(0xffffffffu, rh, d);
      rp += __shfl_xor_sync(0xffffffffu, rp, d);
    }
    if (lane == 0) {
      g_qn[i] = rq;
      g_hn[i] = rh;
      float z = rp + bp0;
      float prob = 0.5f * tanhf(0.5f * z) + 0.5f;   // XLA logistic
      uint32_t bits = random_bits32(kp0, kp1, (unsigned long long)i);
      float u = u01_from_bits(bits);
      g_gens0[i] = (u < prob * anr[r]) ? 1 : 0;
      g_best[i] = 0ull;
    }
  }
}

// ---------- Kernel B: e_active sum + ordered compaction of generators ----------
__global__ void k_listgen(const float* __restrict__ active_edges) {
  const int tid = threadIdx.x;  // 1024
  const int lane = tid & 31, wid = tid >> 5;
  __shared__ float wsumf[32];
  __shared__ int wsum[32];
  __shared__ int wpre[33];

  const float4* ae4 = reinterpret_cast<const float4*>(active_edges);
  float s = 0.f;
#pragma unroll
  for (int r = 0; r < 4; r++) {
    float4 v = ae4[tid + (r << 10)];
    s += v.x + v.y + v.z + v.w;
  }
#pragma unroll
  for (int d = 16; d > 0; d >>= 1) s += __shfl_xor_sync(0xffffffffu, s, d);
  if (lane == 0) wsumf[wid] = s;

  int flags[8];
  int cnt = 0;
#pragma unroll
  for (int r = 0; r < 8; r++) {
    flags[r] = g_gens0[tid * 8 + r];
    cnt += flags[r];
  }
  int incl = warp_incl_scan(cnt, lane);
  if (lane == 31) wsum[wid] = incl;
  __syncthreads();
  if (wid == 0) {
    int v = wsum[lane];
    int sc = warp_incl_scan(v, lane);
    wpre[lane + 1] = sc;
    if (lane == 0) {
      wpre[0] = 0;
      float t = 0.f;
#pragma unroll
      for (int w = 0; w < 32; w++) t += wsumf[w];
      g_eactive = (int)t;
    }
  }
  __syncthreads();
  int off = wpre[wid] + incl - cnt;
#pragma unroll
  for (int r = 0; r < 8; r++) {
    if (flags[r]) {
      g_glist[off] = tid * 8 + r;
      g_flag[off] = 1;
      off++;
    }
  }
  if (tid == 1023) g_ncand = wpre[32];
}

// ---------- Kernel C: persistent chunk x cand-group scoring (R4 body) ----------
__global__ void __launch_bounds__(SEL_THREADS) k_select(const float* __restrict__ nodes,
                                                        const float* __restrict__ active_nodes,
                                                        uint32_t ks0, uint32_t ks1) {
  __shared__ __align__(16) float sh[TILE_J * TILE_STRIDE];
  __shared__ __align__(16) float qsh[CAND_TILE * DD];
  __shared__ float s_qn[CAND_TILE];
  __shared__ int   s_ii[CAND_TILE];
  const int tid = threadIdx.x;
  const int lane = tid & 31;
  const int jj = tid & 127;
  const int grp2 = tid >> 7;
  const int ncand = g_ncand;
  const int ng = (ncand + CAND_TILE - 1) / CAND_TILE;
  const int total = NCHUNK * ng;
  for (int w = blockIdx.x; w < total; w += gridDim.x) {
    const int chunk = w / ng;
    const int grp = w - chunk * ng;
    const int c0 = grp * CAND_TILE;
    const int jbase = chunk << 7;
    {
      const float4* src = reinterpret_cast<const float4*>(nodes + (jbase << 6));
#pragma unroll
      for (int s = 0; s < 8; s++) {
        int idx4 = (s << 8) + tid;
        int row = idx4 >> 4, col4 = idx4 & 15;
        reinterpret_cast<float4*>(sh + row * TILE_STRIDE)[col4] = src[idx4];
      }
    }
    if (tid < CAND_TILE) {
      int idx = c0 + tid;
      int i = (idx < ncand) ? g_glist[idx] : 0;
      s_ii[tid] = i;
      s_qn[tid] = g_qn[i];
    }
#pragma unroll
    for (int s = 0; s < 2; s++) {
      int t4 = (s << 8) + tid;
      int c = t4 >> 4, k4 = t4 & 15;
      int idx = c0 + c;
      float4 qv = (idx < ncand)
          ? reinterpret_cast<const float4*>(g_queries + g_glist[idx] * DD)[k4]
          : make_float4(0.f, 0.f, 0.f, 0.f);
      reinterpret_cast<float4*>(qsh + c * DD)[k4] = qv;
    }
    __syncthreads();
    const int j = jbase + jj;
    const float hn = g_hn[j];
    const float act = active_nodes[j];
    const float4* rowf4 = reinterpret_cast<const float4*>(sh + jj * TILE_STRIDE);
    const int clim = (ncand - c0 < CAND_TILE) ? (ncand - c0) : CAND_TILE;
    const int cbeg = grp2 << 4;
    const int cend = (cbeg + 16 < clim) ? cbeg + 16 : clim;
    for (int c = cbeg; c < cend; c++) {
      const int i = s_ii[c];
      const float4* qf4 = reinterpret_cast<const float4*>(qsh + c * DD);
      float ax = 0.f, ay = 0.f, az = 0.f, aw = 0.f;
#pragma unroll
      for (int kk = 0; kk < 16; kk++) {
        float4 r = rowf4[kk];
        float4 q = qf4[kk];
        ax = fmaf(q.x, r.x, ax);
        ay = fmaf(q.y, r.y, ay);
        az = fmaf(q.z, r.z, az);
        aw = fmaf(q.w, r.w, aw);
      }
      float num = (ax + az) + (ay + aw);
      float sc = num / (sqrtf(s_qn[c] * hn) + 1e-8f);
      sc = fminf(fmaxf(sc, -10000.f), 10000.f);
      if (act <= 0.f) sc = NEGV;
      if (j == i) sc = NEGV;
      unsigned long long lin = (unsigned long long)i * NN + (unsigned long long)j;
      uint32_t bits = random_bits32(ks0, ks1, lin);
      float u = fmaxf(TINYF, u01_from_bits(bits) + TINYF);
      float g = -logf(-logf(u));
      unsigned long long key = enc_key(sc + g, j);
#pragma unroll
      for (int d = 16; d > 0; d >>= 1) {
        unsigned long long o = __shfl_xor_sync(0xffffffffu, key, d);
        if (o > key) key = o;
      }
      if (lane == 0) atomicMax(&g_best[i], key);
    }
    __syncthreads();
  }
}

// ---------- Kernel D: hash-based existing-edge check (1 edge/thread) ----------
__global__ void k_exist(const int* __restrict__ senders, const int* __restrict__ receivers) {
  __shared__ unsigned long long hkey[HASH_SZ];
  __shared__ int hcid[HASH_SZ];
  const int tid = threadIdx.x;  // 256
  const int ncand = g_ncand;
  if (ncand <= HASH_CAP) {
#pragma unroll
    for (int r = 0; r < HASH_SZ / 256; r++) hkey[tid + (r << 8)] = EMPTYK;
    __syncthreads();
    for (int c = tid; c < ncand; c += 256) {
      int i = g_glist[c];
      unsigned long long b = g_best[i];
      uint32_t sel = 0xFFFFFFFFu - (uint32_t)(b & 0xFFFFFFFFull);
      unsigned long long key = ((unsigned long long)(uint32_t)i << 32) | sel;
      uint32_t h = (uint32_t)((key * 0x9E3779B97F4A7C15ull) >> 40) & (HASH_SZ - 1);
      while (true) {
        unsigned long long prev = atomicCAS(&hkey[h], EMPTYK, key);
        if (prev == EMPTYK) { hcid[h] = c; break; }
        h = (h + 1) & (HASH_SZ - 1);
      }
    }
    __syncthreads();
    const int e = (blockIdx.x << 8) + tid;
    unsigned long long ekey =
        ((unsigned long long)(uint32_t)senders[e] << 32) | (uint32_t)receivers[e];
    uint32_t h = (uint32_t)((ekey * 0x9E3779B97F4A7C15ull) >> 40) & (HASH_SZ - 1);
    while (true) {
      unsigned long long k = hkey[h];
      if (k == EMPTYK) break;
      if (k == ekey) { g_flag[hcid[h]] = 0; break; }
      h = (h + 1) & (HASH_SZ - 1);
    }
  } else {
    // fallback: chunked linear compare (not expected with this data)
    for (int base = 0; base < ncand; base += HASH_SZ) {
      int m = ncand - base;
      if (m > HASH_SZ) m = HASH_SZ;
      for (int t = tid; t < m; t += 256) {
        int i = g_glist[base + t];
        unsigned long long b = g_best[i];
        uint32_t sel = 0xFFFFFFFFu - (uint32_t)(b & 0xFFFFFFFFull);
        hkey[t] = ((unsigned long long)(uint32_t)i << 32) | sel;
      }
      __syncthreads();
      const int e = (blockIdx.x << 8) + tid;
      unsigned long long ekey =
          ((unsigned long long)(uint32_t)senders[e] << 32) | (uint32_t)receivers[e];
      for (int k = 0; k < m; k++)
        if (ekey == hkey[k]) g_flag[base + k] = 0;
      __syncthreads();
    }
  }
}

// ---------- Kernel E: final ordered compaction (warp scans) ----------
__global__ void k_compact() {
  const int tid = threadIdx.x;  // 1024
  const int lane = tid & 31, wid = tid >> 5;
  __shared__ int wsum[32];
  __shared__ int wpre[33];
  const int ncand = g_ncand;
  int flags[8];
  int cnt = 0;
#pragma unroll
  for (int r = 0; r < 8; r++) {
    int c = tid * 8 + r;
    flags[r] = (c < ncand) ? g_flag[c] : 0;
    cnt += flags[r];
  }
  int incl = warp_incl_scan(cnt, lane);
  if (lane == 31) wsum[wid] = incl;
  __syncthreads();
  if (wid == 0) {
    int v = wsum[lane];
    int sc = warp_incl_scan(v, lane);
    wpre[lane + 1] = sc;
    if (lane == 0) wpre[0] = 0;
  }
  __syncthreads();
  int off = wpre[wid] + incl - cnt;
#pragma unroll
  for (int r = 0; r < 8; r++) {
    int c = tid * 8 + r;
    if (flags[r]) {
      int i = g_glist[c];
      unsigned long long b = g_best[i];
      g_newsend[off] = i;
      g_newrec[off] = (int)(0xFFFFFFFFu - (uint32_t)(b & 0xFFFFFFFFull));
      off++;
    }
  }
  if (tid == 1023) {
    int total = wpre[32];
    int allowed = EE - g_eactive - 1;
    int n = total < 0 ? 0 : total;
    if (n > allowed) n = allowed;
    g_ngens = n;
  }
}

// ---------- Kernel F: vectorized output writer (MLP=4) ----------
// Layout: [ new_edges (E*D f32) | nsend (E) | nrec (E) | naedges (E) ]
__global__ void k_out4(const float* __restrict__ edges, const int* __restrict__ senders,
                       const int* __restrict__ receivers, float4* __restrict__ out,
                       uint32_t ke0, uint32_t ke1, int n4) {
  const int ngen = g_ngens;
  const int ea = g_eactive;
  const int T1 = EE * DD;
  const int base0 = blockIdx.x * (blockDim.x << 2) + threadIdx.x;
#pragma unroll
  for (int u = 0; u < 4; u++) {
    int idx4 = base0 + u * blockDim.x;
    if (idx4 >= n4) continue;
    int base = idx4 << 2;
    float4 v;
    if (base < T1) {
      v = reinterpret_cast<const float4*>(edges)[idx4];
      int e = base >> 6;
      if (e >= ea && e < ea + ngen) {
        float* vp = reinterpret_cast<float*>(&v);
#pragma unroll
        for (int cmp = 0; cmp < 4; cmp++) {
          uint32_t bits = random_bits32(ke0, ke1, (unsigned long long)(base + cmp));
          float u01 = u01_from_bits(bits);
          const float lo = -0.99999994f;
          float uu = fmaxf(lo, fmaf(u01, 2.0f, lo));
          vp[cmp] += 1.41421356f * xla_erfinv(uu);
        }
      }
    } else if (base < T1 + EE) {
      float* vp = reinterpret_cast<float*>(&v);
#pragma unroll
      for (int cmp = 0; cmp < 4; cmp++) {
        int j = base + cmp - T1;
        float x;
        if (j < ea)             x = (float)senders[j];
        else if (j < ea + ngen) x = (float)g_newsend[j - ea];
        else                    x = (float)(NN - 1);
        vp[cmp] = x;
      }
    } else if (base < T1 + 2 * EE) {
      float* vp = reinterpret_cast<float*>(&v);
#pragma unroll
      for (int cmp = 0; cmp < 4; cmp++) {
        int j = base + cmp - T1 - EE;
        float x;
        if (j < ea)             x = (float)receivers[j];
        else if (j < ea + ngen) x = (float)g_newrec[j - ea];
        else                    x = (float)(NN - 1);
        vp[cmp] = x;
      }
    } else {
      float* vp = reinterpret_cast<float*>(&v);
#pragma unroll
      for (int cmp = 0; cmp < 4; cmp++) {
        int j = base + cmp - T1 - 2 * EE;
        vp[cmp] = (j < ea + ngen) ? 1.0f : 0.0f;
      }
    }
    out[idx4] = v;
  }
}

// fallback scalar writer (out_size % 4 != 0 — not expected)
__global__ void k_out1(const float* __restrict__ edges, const int* __restrict__ senders,
                       const int* __restrict__ receivers, float* __restrict__ out,
                       uint32_t ke0, uint32_t ke1, int start, int out_size) {
  int idx = start + blockIdx.x * blockDim.x + threadIdx.x;
  if (idx >= out_size) return;
  const int ngen = g_ngens;
  const int ea = g_eactive;
  const int T1 = EE * DD;
  float x = 0.f;
  if (idx < T1) {
    x = edges[idx];
    int e = idx >> 6;
    if (e >= ea && e < ea + ngen) {
      uint32_t bits = random_bits32(ke0, ke1, (unsigned long long)idx);
      float u01 = u01_from_bits(bits);
      const float lo = -0.99999994f;
      float u = fmaxf(lo, fmaf(u01, 2.0f, lo));
      x += 1.41421356f * xla_erfinv(u);
    }
  } else if (idx < T1 + EE) {
    int j = idx - T1;
    if (j < ea)             x = (float)senders[j];
    else if (j < ea + ngen) x = (float)g_newsend[j - ea];
    else                    x = (float)(NN - 1);
  } else if (idx < T1 + 2 * EE) {
    int j = idx - T1 - EE;
    if (j < ea)             x = (float)receivers[j];
    else if (j < ea + ngen) x = (float)g_newrec[j - ea];
    else                    x = (float)(NN - 1);
  } else if (idx < T1 + 3 * EE) {
    int j = idx - T1 - 2 * EE;
    x = (j < ea + ngen) ? 1.0f : 0.0f;
  }
  out[idx] = x;
}

// ---------------- host ----------------
extern "C" void kernel_launch(void* const* d_in, const int* in_sizes, int n_in,
                              void* d_out, int out_size) {
  const float* nodes        = (const float*)d_in[0];
  const float* edges        = (const float*)d_in[1];
  const int*   receivers    = (const int*)d_in[2];
  const int*   senders      = (const int*)d_in[3];
  const float* active_nodes = (const float*)d_in[4];
  const float* active_edges = (const float*)d_in[5];
  const float* Wq           = (const float*)d_in[6];
  const float* bq           = (const float*)d_in[7];
  const float* Wp           = (const float*)d_in[8];
  const float* bp           = (const float*)d_in[9];
  (void)in_sizes; (void)n_in;

  const uint32_t K0 = 0u, K1 = 42u;
  uint32_t kp0, kp1, ke0, ke1, ks0, ks1;
  threefry2x32(K0, K1, 0u, 0u, &kp0, &kp1);  // key_prob
  threefry2x32(K0, K1, 0u, 1u, &ke0, &ke1);  // key_edges
  threefry2x32(K0, K1, 0u, 2u, &ks0, &ks1);  // key_samp

  k_prep<<<NN / 64, 512>>>(nodes, Wq, bq, Wp, bp, active_nodes, kp0, kp1);
  k_listgen<<<1, 1024>>>(active_edges);
  k_select<<<592, SEL_THREADS>>>(nodes, active_nodes, ks0, ks1);
  k_exist<<<EE / 256, 256>>>(senders, receivers);
  k_compact<<<1, 1024>>>();

  int n4 = out_size >> 2;
  if (n4 > 0) {
    int blocks = (n4 + 1023) / 1024;
    k_out4<<<blocks, 256>>>(edges, senders, receivers, (float4*)d_out, ke0, ke1, n4);
  }
  int rem_start = n4 << 2;
  if (rem_start < out_size)
    k_out1<<<1, 256>>>(edges, senders, receivers, (float*)d_out, ke0, ke1,
                       rem_start, out_size);
}

// round 10
// speedup vs baseline: 2.2080x; 1.0343x over previous
#include <cuda_runtime.h>
#include <cstdint>

#define NN 8192
#define DD 64
#define EE 16384
#define NEGV -1e10f
#define TINYF 1.17549435e-38f

#define SEL_THREADS 256
#define TILE_J 128
#define TILE_STRIDE 68          // floats; 272B rows -> 16B aligned, LDS.128 conflict-free
#define NCHUNK (NN / TILE_J)    // 64
#define CAND_TILE 32
#define NMASKW 256              // 8192 bits
#define HASH_SZ 2048
#define HASH_CAP 1536
#define EMPTYK 0xFFFFFFFFFFFFFFFFull

// ---------------- scratch ----------------
__device__ float g_queries[NN * DD];
__device__ float g_qn[NN];
__device__ float g_hn[NN];
__device__ uint32_t g_gensmask[NMASKW];
__device__ int   g_glist[NN];
__device__ int   g_flag[NN];
__device__ unsigned long long g_best[NN];
__device__ int   g_newsend[NN];
__device__ int   g_newrec[NN];
__device__ int   g_ngens;
__device__ int   g_eactive;
__device__ int   g_ncand;

// ---------------- threefry2x32 (JAX-exact) ----------------
__host__ __device__ __forceinline__ void threefry2x32(uint32_t k0, uint32_t k1,
                                                      uint32_t x0, uint32_t x1,
                                                      uint32_t* o0, uint32_t* o1) {
  uint32_t ks2 = k0 ^ k1 ^ 0x1BD11BDAu;
#define ROTL32(v, r) (((v) << (r)) | ((v) >> (32 - (r))))
#define TFRND(r) { x0 += x1; x1 = ROTL32(x1, r); x1 ^= x0; }
  x0 += k0; x1 += k1;
  TFRND(13) TFRND(15) TFRND(26) TFRND(6)
  x0 += k1; x1 += ks2 + 1u;
  TFRND(17) TFRND(29) TFRND(16) TFRND(24)
  x0 += ks2; x1 += k0 + 2u;
  TFRND(13) TFRND(15) TFRND(26) TFRND(6)
  x0 += k0; x1 += k1 + 3u;
  TFRND(17) TFRND(29) TFRND(16) TFRND(24)
  x0 += k1; x1 += ks2 + 4u;
  TFRND(13) TFRND(15) TFRND(26) TFRND(6)
  x0 += ks2; x1 += k0 + 5u;
  *o0 = x0; *o1 = x1;
#undef TFRND
#undef ROTL32
}

__device__ __forceinline__ uint32_t random_bits32(uint32_t k0, uint32_t k1,
                                                  unsigned long long idx) {
  uint32_t o0, o1;
  threefry2x32(k0, k1, (uint32_t)(idx >> 32), (uint32_t)idx, &o0, &o1);
  return o0 ^ o1;
}

__device__ __forceinline__ float u01_from_bits(uint32_t bits) {
  return __uint_as_float((bits >> 9) | 0x3f800000u) - 1.0f;
}

// XLA ErfInv (Giles)
__device__ __forceinline__ float xla_erfinv(float x) {
  float w = -log1pf(-x * x);
  float p;
  if (w < 5.f) {
    w -= 2.5f;
    p = 2.81022636e-08f;
    p = fmaf(p, w, 3.43273939e-07f);
    p = fmaf(p, w, -3.5233877e-06f);
    p = fmaf(p, w, -4.39150654e-06f);
    p = fmaf(p, w, 0.00021858087f);
    p = fmaf(p, w, -0.00125372503f);
    p = fmaf(p, w, -0.00417768164f);
    p = fmaf(p, w, 0.246640727f);
    p = fmaf(p, w, 1.50140941f);
  } else {
    w = sqrtf(w) - 3.f;
    p = -0.000200214257f;
    p = fmaf(p, w, 0.000100950558f);
    p = fmaf(p, w, 0.00134934322f);
    p = fmaf(p, w, -0.00367342844f);
    p = fmaf(p, w, 0.00573950773f);
    p = fmaf(p, w, -0.0076224613f);
    p = fmaf(p, w, 0.00943887047f);
    p = fmaf(p, w, 1.00167406f);
    p = fmaf(p, w, 2.83297682f);
  }
  return p * x;
}

__device__ __forceinline__ unsigned long long enc_key(float v, int j) {
  uint32_t u = __float_as_uint(v);
  u = (u & 0x80000000u) ? ~u : (u | 0x80000000u);
  return ((unsigned long long)u << 32) | (unsigned long long)(0xFFFFFFFFu - (uint32_t)j);
}

__device__ __forceinline__ int warp_incl_scan(int v, int lane) {
#pragma unroll
  for (int d = 1; d < 32; d <<= 1) {
    int o = __shfl_up_sync(0xffffffffu, v, d);
    if (lane >= d) v += o;
  }
  return v;
}

// ---------- Kernel A: prep (R9 body) + generator bitmask ----------
__global__ void __launch_bounds__(512) k_prep(const float* __restrict__ nodes,
                                              const float* __restrict__ Wq,
                                              const float* __restrict__ bq,
                                              const float* __restrict__ Wp,
                                              const float* __restrict__ bp,
                                              const float* __restrict__ active_nodes,
                                              uint32_t kp0, uint32_t kp1) {
  __shared__ __align__(16) float sWq[DD * DD];
  __shared__ float sbq[DD];
  __shared__ float sWp[DD];
  __shared__ int   sgen[64];
  const int tid = threadIdx.x;
  const int warp = tid >> 5, lane = tid & 31;
  {
    const float4* w4 = reinterpret_cast<const float4*>(Wq);
    float4* s4 = reinterpret_cast<float4*>(sWq);
#pragma unroll
    for (int r = 0; r < 2; r++) s4[tid + (r << 9)] = w4[tid + (r << 9)];
    if (tid < DD) { sbq[tid] = bq[tid]; sWp[tid] = Wp[tid]; }
  }
  const int ibase = (blockIdx.x << 6) + (warp << 2);
  float2 n2r[4];
#pragma unroll
  for (int r = 0; r < 4; r++)
    n2r[r] = reinterpret_cast<const float2*>(nodes + (ibase + r) * DD)[lane];
  float anr[4];
#pragma unroll
  for (int r = 0; r < 4; r++) anr[r] = active_nodes[ibase + r];
  __syncthreads();
  const float2 b2 = reinterpret_cast<const float2*>(sbq)[lane];
  const float2 wp2 = reinterpret_cast<const float2*>(sWp)[lane];
  const float bp0 = bp[0];
#pragma unroll
  for (int r = 0; r < 4; r++) {
    const int i = ibase + r;
    const float2 n2 = n2r[r];
    float q0 = b2.x, q1 = b2.y;
#pragma unroll
    for (int k = 0; k < DD; k++) {
      float nk = __shfl_sync(0xffffffffu, (k & 1) ? n2.y : n2.x, k >> 1);
      float2 w = reinterpret_cast<const float2*>(sWq + k * DD)[lane];
      q0 = fmaf(nk, w.x, q0);
      q1 = fmaf(nk, w.y, q1);
    }
    reinterpret_cast<float2*>(g_queries + i * DD)[lane] = make_float2(q0, q1);
    float rq = q0 * q0 + q1 * q1;
    float rh = n2.x * n2.x + n2.y * n2.y;
    float rp = n2.x * wp2.x + n2.y * wp2.y;
#pragma unroll
    for (int d = 16; d > 0; d >>= 1) {
      rq += __shfl_xor_sync(0xffffffffu, rq, d);
      rh += __shfl_xor_sync(0xffffffffu, rh, d);
      rp += __shfl_xor_sync(0xffffffffu, rp, d);
    }
    if (lane == 0) {
      g_qn[i] = rq;
      g_hn[i] = rh;
      float z = rp + bp0;
      float prob = 0.5f * tanhf(0.5f * z) + 0.5f;   // XLA logistic
      uint32_t bits = random_bits32(kp0, kp1, (unsigned long long)i);
      float u = u01_from_bits(bits);
      sgen[(warp << 2) + r] = (u < prob * anr[r]) ? 1 : 0;
      g_best[i] = 0ull;
    }
  }
  __syncthreads();
  if (tid < 2) {
    uint32_t w = 0;
#pragma unroll
    for (int k = 0; k < 32; k++) w |= (uint32_t)sgen[(tid << 5) + k] << k;
    g_gensmask[(blockIdx.x << 1) + tid] = w;
  }
}

// ---------- Kernel B: select — derives its candidate window from the bitmask ----------
__global__ void __launch_bounds__(SEL_THREADS) k_select(const float* __restrict__ nodes,
                                                        const float* __restrict__ active_nodes,
                                                        uint32_t ks0, uint32_t ks1) {
  __shared__ __align__(16) float sh[TILE_J * TILE_STRIDE];
  __shared__ __align__(16) float qsh[CAND_TILE * DD];
  __shared__ float s_qn[CAND_TILE];
  __shared__ int   s_ii[CAND_TILE];
  __shared__ int   s_glist[CAND_TILE];
  __shared__ int   s_wsum[8];
  const int tid = threadIdx.x;
  const int lane = tid & 31;
  const int wid = tid >> 5;
  const int jj = tid & 127;
  const int grp2 = tid >> 7;

  // --- derive ncand + per-word rank from the generator bitmask ---
  const uint32_t mw = g_gensmask[tid];          // 256 words, 1/thread
  const int cnt = __popc(mw);
  int incl = warp_incl_scan(cnt, lane);
  if (lane == 31) s_wsum[wid] = incl;
  __syncthreads();
  int wbase = 0, ncand = 0;
#pragma unroll
  for (int w = 0; w < 8; w++) {
    int v = s_wsum[w];
    if (w < wid) wbase += v;
    ncand += v;
  }
  const int mypre = wbase + incl - cnt;         // rank of my word's first set bit

  const int ng = (ncand + CAND_TILE - 1) / CAND_TILE;
  const int total = NCHUNK * ng;
  for (int w = blockIdx.x; w < total; w += gridDim.x) {
    const int chunk = w / ng;
    const int grp = w - chunk * ng;
    const int c0 = grp * CAND_TILE;
    const int jbase = chunk << 7;
    // emit this block's candidate window [c0, c0+32)
    if (cnt) {
      uint32_t m = mw;
      int r = mypre;
      while (m) {
        int b = __ffs((int)m) - 1;
        if (r >= c0 && r < c0 + CAND_TILE) s_glist[r - c0] = (tid << 5) + b;
        m &= m - 1;
        r++;
      }
    }
    __syncthreads();
    {
      const float4* src = reinterpret_cast<const float4*>(nodes + (jbase << 6));
#pragma unroll
      for (int s = 0; s < 8; s++) {
        int idx4 = (s << 8) + tid;
        int row = idx4 >> 4, col4 = idx4 & 15;
        reinterpret_cast<float4*>(sh + row * TILE_STRIDE)[col4] = src[idx4];
      }
    }
    if (tid < CAND_TILE) {
      int idx = c0 + tid;
      int i = (idx < ncand) ? s_glist[tid] : 0;
      s_ii[tid] = i;
      s_qn[tid] = g_qn[i];
    }
#pragma unroll
    for (int s = 0; s < 2; s++) {
      int t4 = (s << 8) + tid;
      int c = t4 >> 4, k4 = t4 & 15;
      int idx = c0 + c;
      float4 qv = (idx < ncand)
          ? reinterpret_cast<const float4*>(g_queries + s_glist[c] * DD)[k4]
          : make_float4(0.f, 0.f, 0.f, 0.f);
      reinterpret_cast<float4*>(qsh + c * DD)[k4] = qv;
    }
    __syncthreads();
    const int j = jbase + jj;
    const float hn = g_hn[j];
    const float act = active_nodes[j];
    const float4* rowf4 = reinterpret_cast<const float4*>(sh + jj * TILE_STRIDE);
    const int clim = (ncand - c0 < CAND_TILE) ? (ncand - c0) : CAND_TILE;
    const int cbeg = grp2 << 4;
    const int cend = (cbeg + 16 < clim) ? cbeg + 16 : clim;
    for (int c = cbeg; c < cend; c++) {
      const int i = s_ii[c];
      const float4* qf4 = reinterpret_cast<const float4*>(qsh + c * DD);
      float ax = 0.f, ay = 0.f, az = 0.f, aw = 0.f;
#pragma unroll
      for (int kk = 0; kk < 16; kk++) {
        float4 r = rowf4[kk];
        float4 q = qf4[kk];
        ax = fmaf(q.x, r.x, ax);
        ay = fmaf(q.y, r.y, ay);
        az = fmaf(q.z, r.z, az);
        aw = fmaf(q.w, r.w, aw);
      }
      float num = (ax + az) + (ay + aw);
      float sc = num / (sqrtf(s_qn[c] * hn) + 1e-8f);
      sc = fminf(fmaxf(sc, -10000.f), 10000.f);
      if (act <= 0.f) sc = NEGV;
      if (j == i) sc = NEGV;
      unsigned long long lin = (unsigned long long)i * NN + (unsigned long long)j;
      uint32_t bits = random_bits32(ks0, ks1, lin);
      float u = fmaxf(TINYF, u01_from_bits(bits) + TINYF);
      float g = -logf(-logf(u));
      unsigned long long key = enc_key(sc + g, j);
#pragma unroll
      for (int d = 16; d > 0; d >>= 1) {
        unsigned long long o = __shfl_xor_sync(0xffffffffu, key, d);
        if (o > key) key = o;
      }
      if (lane == 0) atomicMax(&g_best[i], key);
    }
    __syncthreads();
  }
}

// ---- Kernel C: e_active + glist + exist-hash + compaction, ONE block ----
__global__ void __launch_bounds__(1024) k_cc(const float* __restrict__ active_edges,
                                             const int* __restrict__ senders,
                                             const int* __restrict__ receivers) {
  __shared__ unsigned long long hkey[HASH_SZ];
  __shared__ int   hcid[HASH_SZ];
  __shared__ float swF[32];
  __shared__ int   swA[32];
  __shared__ int   pre[33];
  const int tid = threadIdx.x;  // 1024
  const int lane = tid & 31, wid = tid >> 5;

  // e_active sum
  {
    const float4* ae4 = reinterpret_cast<const float4*>(active_edges);
    float s = 0.f;
#pragma unroll
    for (int r = 0; r < 4; r++) {
      float4 v = ae4[tid + (r << 10)];
      s += v.x + v.y + v.z + v.w;
    }
#pragma unroll
    for (int d = 16; d > 0; d >>= 1) s += __shfl_xor_sync(0xffffffffu, s, d);
    if (lane == 0) swF[wid] = s;
  }
  // glist derivation from bitmask (threads 0..255 hold words)
  const uint32_t mw = (tid < NMASKW) ? g_gensmask[tid] : 0u;
  const int cnt = __popc(mw);
  int incl = warp_incl_scan(cnt, lane);
  if (lane == 31) swA[wid] = incl;
  __syncthreads();
  if (tid == 0) {
    pre[0] = 0;
#pragma unroll
    for (int w = 0; w < 32; w++) pre[w + 1] = pre[w] + swA[w];
    g_ncand = pre[32];
    float t = 0.f;
#pragma unroll
    for (int w = 0; w < 32; w++) t += swF[w];
    g_eactive = (int)t;
  }
  __syncthreads();
  const int ncand = pre[32];
  {
    int r = pre[wid] + incl - cnt;
    uint32_t m = mw;
    while (m) {
      int b = __ffs((int)m) - 1;
      g_glist[r] = (tid << 5) + b;
      g_flag[r] = 1;
      m &= m - 1;
      r++;
    }
  }
  __syncthreads();

  // exist-check
  if (ncand <= HASH_CAP) {
#pragma unroll
    for (int r = 0; r < HASH_SZ / 1024; r++) hkey[tid + (r << 10)] = EMPTYK;
    __syncthreads();
    for (int c = tid; c < ncand; c += 1024) {
      int i = g_glist[c];
      unsigned long long b = g_best[i];
      uint32_t sel = 0xFFFFFFFFu - (uint32_t)(b & 0xFFFFFFFFull);
      unsigned long long key = ((unsigned long long)(uint32_t)i << 32) | sel;
      uint32_t h = (uint32_t)((key * 0x9E3779B97F4A7C15ull) >> 40) & (HASH_SZ - 1);
      while (true) {
        unsigned long long prev = atomicCAS(&hkey[h], EMPTYK, key);
        if (prev == EMPTYK) { hcid[h] = c; break; }
        h = (h + 1) & (HASH_SZ - 1);
      }
    }
    __syncthreads();
    const int4* s4 = reinterpret_cast<const int4*>(senders);
    const int4* r4 = reinterpret_cast<const int4*>(receivers);
#pragma unroll
    for (int r = 0; r < EE / 4 / 1024; r++) {      // 4 iters
      int idx4 = tid + (r << 10);
      int4 sv = s4[idx4];
      int4 rv = r4[idx4];
      const int ss[4] = {sv.x, sv.y, sv.z, sv.w};
      const int rr[4] = {rv.x, rv.y, rv.z, rv.w};
#pragma unroll
      for (int q = 0; q < 4; q++) {
        unsigned long long key =
            ((unsigned long long)(uint32_t)ss[q] << 32) | (uint32_t)rr[q];
        uint32_t h = (uint32_t)((key * 0x9E3779B97F4A7C15ull) >> 40) & (HASH_SZ - 1);
        while (true) {
          unsigned long long k = hkey[h];
          if (k == EMPTYK) break;
          if (k == key) { g_flag[hcid[h]] = 0; break; }
          h = (h + 1) & (HASH_SZ - 1);
        }
      }
    }
    __syncthreads();
  } else {
    // fallback (never expected): per-candidate linear scan
    for (int c = tid; c < ncand; c += 1024) {
      int i = g_glist[c];
      unsigned long long b = g_best[i];
      uint32_t sel = 0xFFFFFFFFu - (uint32_t)(b & 0xFFFFFFFFull);
      int found = 0;
      for (int e = 0; e < EE; e++)
        found |= (senders[e] == i && (uint32_t)receivers[e] == sel);
      if (found) g_flag[c] = 0;
    }
    __syncthreads();
  }

  // compaction (ordered)
  int flags[8];
  int ccnt = 0;
#pragma unroll
  for (int r = 0; r < 8; r++) {
    int c = tid * 8 + r;
    flags[r] = (c < ncand) ? g_flag[c] : 0;
    ccnt += flags[r];
  }
  int cincl = warp_incl_scan(ccnt, lane);
  if (lane == 31) swA[wid] = cincl;
  __syncthreads();
  if (tid == 0) {
    pre[0] = 0;
#pragma unroll
    for (int w = 0; w < 32; w++) pre[w + 1] = pre[w] + swA[w];
    int total = pre[32];
    int allowed = EE - g_eactive - 1;
    int n = total < 0 ? 0 : total;
    if (n > allowed) n = allowed;
    g_ngens = n;
  }
  __syncthreads();
  int off = pre[wid] + cincl - ccnt;
#pragma unroll
  for (int r = 0; r < 8; r++) {
    int c = tid * 8 + r;
    if (flags[r]) {
      int i = g_glist[c];
      unsigned long long b = g_best[i];
      g_newsend[off] = i;
      g_newrec[off] = (int)(0xFFFFFFFFu - (uint32_t)(b & 0xFFFFFFFFull));
      off++;
    }
  }
}

// ---------- Kernel D: vectorized output writer (MLP=4) ----------
// Layout: [ new_edges (E*D f32) | nsend (E) | nrec (E) | naedges (E) ]
__global__ void k_out4(const float* __restrict__ edges, const int* __restrict__ senders,
                       const int* __restrict__ receivers, float4* __restrict__ out,
                       uint32_t ke0, uint32_t ke1, int n4) {
  const int ngen = g_ngens;
  const int ea = g_eactive;
  const int T1 = EE * DD;
  const int base0 = blockIdx.x * (blockDim.x << 2) + threadIdx.x;
#pragma unroll
  for (int u = 0; u < 4; u++) {
    int idx4 = base0 + u * blockDim.x;
    if (idx4 >= n4) continue;
    int base = idx4 << 2;
    float4 v;
    if (base < T1) {
      v = reinterpret_cast<const float4*>(edges)[idx4];
      int e = base >> 6;
      if (e >= ea && e < ea + ngen) {
        float* vp = reinterpret_cast<float*>(&v);
#pragma unroll
        for (int cmp = 0; cmp < 4; cmp++) {
          uint32_t bits = random_bits32(ke0, ke1, (unsigned long long)(base + cmp));
          float u01 = u01_from_bits(bits);
          const float lo = -0.99999994f;
          float uu = fmaxf(lo, fmaf(u01, 2.0f, lo));
          vp[cmp] += 1.41421356f * xla_erfinv(uu);
        }
      }
    } else if (base < T1 + EE) {
      float* vp = reinterpret_cast<float*>(&v);
#pragma unroll
      for (int cmp = 0; cmp < 4; cmp++) {
        int j = base + cmp - T1;
        float x;
        if (j < ea)             x = (float)senders[j];
        else if (j < ea + ngen) x = (float)g_newsend[j - ea];
        else                    x = (float)(NN - 1);
        vp[cmp] = x;
      }
    } else if (base < T1 + 2 * EE) {
      float* vp = reinterpret_cast<float*>(&v);
#pragma unroll
      for (int cmp = 0; cmp < 4; cmp++) {
        int j = base + cmp - T1 - EE;
        float x;
        if (j < ea)             x = (float)receivers[j];
        else if (j < ea + ngen) x = (float)g_newrec[j - ea];
        else                    x = (float)(NN - 1);
        vp[cmp] = x;
      }
    } else {
      float* vp = reinterpret_cast<float*>(&v);
#pragma unroll
      for (int cmp = 0; cmp < 4; cmp++) {
        int j = base + cmp - T1 - 2 * EE;
        vp[cmp] = (j < ea + ngen) ? 1.0f : 0.0f;
      }
    }
    out[idx4] = v;
  }
}

// fallback scalar writer (out_size % 4 != 0 — not expected)
__global__ void k_out1(const float* __restrict__ edges, const int* __restrict__ senders,
                       const int* __restrict__ receivers, float* __restrict__ out,
                       uint32_t ke0, uint32_t ke1, int start, int out_size) {
  int idx = start + blockIdx.x * blockDim.x + threadIdx.x;
  if (idx >= out_size) return;
  const int ngen = g_ngens;
  const int ea = g_eactive;
  const int T1 = EE * DD;
  float x = 0.f;
  if (idx < T1) {
    x = edges[idx];
    int e = idx >> 6;
    if (e >= ea && e < ea + ngen) {
      uint32_t bits = random_bits32(ke0, ke1, (unsigned long long)idx);
      float u01 = u01_from_bits(bits);
      const float lo = -0.99999994f;
      float u = fmaxf(lo, fmaf(u01, 2.0f, lo));
      x += 1.41421356f * xla_erfinv(u);
    }
  } else if (idx < T1 + EE) {
    int j = idx - T1;
    if (j < ea)             x = (float)senders[j];
    else if (j < ea + ngen) x = (float)g_newsend[j - ea];
    else                    x = (float)(NN - 1);
  } else if (idx < T1 + 2 * EE) {
    int j = idx - T1 - EE;
    if (j < ea)             x = (float)receivers[j];
    else if (j < ea + ngen) x = (float)g_newrec[j - ea];
    else                    x = (float)(NN - 1);
  } else if (idx < T1 + 3 * EE) {
    int j = idx - T1 - 2 * EE;
    x = (j < ea + ngen) ? 1.0f : 0.0f;
  }
  out[idx] = x;
}

// ---------------- host ----------------
extern "C" void kernel_launch(void* const* d_in, const int* in_sizes, int n_in,
                              void* d_out, int out_size) {
  const float* nodes        = (const float*)d_in[0];
  const float* edges        = (const float*)d_in[1];
  const int*   receivers    = (const int*)d_in[2];
  const int*   senders      = (const int*)d_in[3];
  const float* active_nodes = (const float*)d_in[4];
  const float* active_edges = (const float*)d_in[5];
  const float* Wq           = (const float*)d_in[6];
  const float* bq           = (const float*)d_in[7];
  const float* Wp           = (const float*)d_in[8];
  const float* bp           = (const float*)d_in[9];
  (void)in_sizes; (void)n_in;

  const uint32_t K0 = 0u, K1 = 42u;
  uint32_t kp0, kp1, ke0, ke1, ks0, ks1;
  threefry2x32(K0, K1, 0u, 0u, &kp0, &kp1);  // key_prob
  threefry2x32(K0, K1, 0u, 1u, &ke0, &ke1);  // key_edges
  threefry2x32(K0, K1, 0u, 2u, &ks0, &ks1);  // key_samp

  k_prep<<<NN / 64, 512>>>(nodes, Wq, bq, Wp, bp, active_nodes, kp0, kp1);
  k_select<<<592, SEL_THREADS>>>(nodes, active_nodes, ks0, ks1);
  k_cc<<<1, 1024>>>(active_edges, senders, receivers);

  int n4 = out_size >> 2;
  if (n4 > 0) {
    int blocks = (n4 + 1023) / 1024;
    k_out4<<<blocks, 256>>>(edges, senders, receivers, (float4*)d_out, ke0, ke1, n4);
  }
  int rem_start = n4 << 2;
  if (rem_start < out_size)
    k_out1<<<1, 256>>>(edges, senders, receivers, (float*)d_out, ke0, ke1,
                       rem_start, out_size);
}

// round 12
// speedup vs baseline: 2.3147x; 1.0483x over previous
#include <cuda_runtime.h>
#include <cstdint>

#define NN 8192
#define DD 64
#define EE 16384
#define NEGV -1e10f
#define TINYF 1.17549435e-38f

#define SEL_THREADS 256
#define TILE_J 128
#define TILE_STRIDE 68          // floats; 272B rows -> 16B aligned, LDS.128 conflict-free
#define NCHUNK (NN / TILE_J)    // 64
#define CAND_TILE 32
#define NMASKW 256              // 8192 bits
#define HASH_SZ 2048
#define HASH_CAP 1536
#define EMPTYK 0xFFFFFFFFFFFFFFFFull

// ---------------- scratch ----------------
__device__ float g_queries[NN * DD];
__device__ float g_qn[NN];
__device__ float g_hn[NN];
__device__ uint32_t g_gensmask[NMASKW];
__device__ int   g_glist[NN];
__device__ int   g_flag[NN];
__device__ unsigned long long g_best[NN];
__device__ int   g_newsend[NN];
__device__ int   g_newrec[NN];
__device__ int   g_ngens;
__device__ int   g_eactive;
__device__ int   g_ncand;

// ---------------- threefry2x32 (JAX-exact) ----------------
__host__ __device__ __forceinline__ void threefry2x32(uint32_t k0, uint32_t k1,
                                                      uint32_t x0, uint32_t x1,
                                                      uint32_t* o0, uint32_t* o1) {
  uint32_t ks2 = k0 ^ k1 ^ 0x1BD11BDAu;
#define ROTL32(v, r) (((v) << (r)) | ((v) >> (32 - (r))))
#define TFRND(r) { x0 += x1; x1 = ROTL32(x1, r); x1 ^= x0; }
  x0 += k0; x1 += k1;
  TFRND(13) TFRND(15) TFRND(26) TFRND(6)
  x0 += k1; x1 += ks2 + 1u;
  TFRND(17) TFRND(29) TFRND(16) TFRND(24)
  x0 += ks2; x1 += k0 + 2u;
  TFRND(13) TFRND(15) TFRND(26) TFRND(6)
  x0 += k0; x1 += k1 + 3u;
  TFRND(17) TFRND(29) TFRND(16) TFRND(24)
  x0 += k1; x1 += ks2 + 4u;
  TFRND(13) TFRND(15) TFRND(26) TFRND(6)
  x0 += ks2; x1 += k0 + 5u;
  *o0 = x0; *o1 = x1;
#undef TFRND
#undef ROTL32
}

__device__ __forceinline__ uint32_t random_bits32(uint32_t k0, uint32_t k1,
                                                  unsigned long long idx) {
  uint32_t o0, o1;
  threefry2x32(k0, k1, (uint32_t)(idx >> 32), (uint32_t)idx, &o0, &o1);
  return o0 ^ o1;
}

__device__ __forceinline__ float u01_from_bits(uint32_t bits) {
  return __uint_as_float((bits >> 9) | 0x3f800000u) - 1.0f;
}

// XLA ErfInv (Giles)
__device__ __forceinline__ float xla_erfinv(float x) {
  float w = -log1pf(-x * x);
  float p;
  if (w < 5.f) {
    w -= 2.5f;
    p = 2.81022636e-08f;
    p = fmaf(p, w, 3.43273939e-07f);
    p = fmaf(p, w, -3.5233877e-06f);
    p = fmaf(p, w, -4.39150654e-06f);
    p = fmaf(p, w, 0.00021858087f);
    p = fmaf(p, w, -0.00125372503f);
    p = fmaf(p, w, -0.00417768164f);
    p = fmaf(p, w, 0.246640727f);
    p = fmaf(p, w, 1.50140941f);
  } else {
    w = sqrtf(w) - 3.f;
    p = -0.000200214257f;
    p = fmaf(p, w, 0.000100950558f);
    p = fmaf(p, w, 0.00134934322f);
    p = fmaf(p, w, -0.00367342844f);
    p = fmaf(p, w, 0.00573950773f);
    p = fmaf(p, w, -0.0076224613f);
    p = fmaf(p, w, 0.00943887047f);
    p = fmaf(p, w, 1.00167406f);
    p = fmaf(p, w, 2.83297682f);
  }
  return p * x;
}

__device__ __forceinline__ unsigned long long enc_key(float v, int j) {
  uint32_t u = __float_as_uint(v);
  u = (u & 0x80000000u) ? ~u : (u | 0x80000000u);
  return ((unsigned long long)u << 32) | (unsigned long long)(0xFFFFFFFFu - (uint32_t)j);
}

__device__ __forceinline__ int warp_incl_scan(int v, int lane) {
#pragma unroll
  for (int d = 1; d < 32; d <<= 1) {
    int o = __shfl_up_sync(0xffffffffu, v, d);
    if (lane >= d) v += o;
  }
  return v;
}

// ---------- Kernel A: prep + generator bitmask ----------
__global__ void __launch_bounds__(512) k_prep(const float* __restrict__ nodes,
                                              const float* __restrict__ Wq,
                                              const float* __restrict__ bq,
                                              const float* __restrict__ Wp,
                                              const float* __restrict__ bp,
                                              const float* __restrict__ active_nodes,
                                              uint32_t kp0, uint32_t kp1) {
  __shared__ __align__(16) float sWq[DD * DD];
  __shared__ float sbq[DD];
  __shared__ float sWp[DD];
  __shared__ int   sgen[64];
  const int tid = threadIdx.x;
  const int warp = tid >> 5, lane = tid & 31;
  {
    const float4* w4 = reinterpret_cast<const float4*>(Wq);
    float4* s4 = reinterpret_cast<float4*>(sWq);
#pragma unroll
    for (int r = 0; r < 2; r++) s4[tid + (r << 9)] = w4[tid + (r << 9)];
    if (tid < DD) { sbq[tid] = bq[tid]; sWp[tid] = Wp[tid]; }
  }
  const int ibase = (blockIdx.x << 6) + (warp << 2);
  float2 n2r[4];
#pragma unroll
  for (int r = 0; r < 4; r++)
    n2r[r] = reinterpret_cast<const float2*>(nodes + (ibase + r) * DD)[lane];
  float anr[4];
#pragma unroll
  for (int r = 0; r < 4; r++) anr[r] = active_nodes[ibase + r];
  __syncthreads();
  const float2 b2 = reinterpret_cast<const float2*>(sbq)[lane];
  const float2 wp2 = reinterpret_cast<const float2*>(sWp)[lane];
  const float bp0 = bp[0];
#pragma unroll
  for (int r = 0; r < 4; r++) {
    const int i = ibase + r;
    const float2 n2 = n2r[r];
    float q0 = b2.x, q1 = b2.y;
#pragma unroll
    for (int k = 0; k < DD; k++) {
      float nk = __shfl_sync(0xffffffffu, (k & 1) ? n2.y : n2.x, k >> 1);
      float2 w = reinterpret_cast<const float2*>(sWq + k * DD)[lane];
      q0 = fmaf(nk, w.x, q0);
      q1 = fmaf(nk, w.y, q1);
    }
    reinterpret_cast<float2*>(g_queries + i * DD)[lane] = make_float2(q0, q1);
    float rq = q0 * q0 + q1 * q1;
    float rh = n2.x * n2.x + n2.y * n2.y;
    float rp = n2.x * wp2.x + n2.y * wp2.y;
#pragma unroll
    for (int d = 16; d > 0; d >>= 1) {
      rq += __shfl_xor_sync(0xffffffffu, rq, d);
      rh += __shfl_xor_sync(0xffffffffu, rh, d);
      rp += __shfl_xor_sync(0xffffffffu, rp, d);
    }
    if (lane == 0) {
      g_qn[i] = rq;
      g_hn[i] = rh;
      float z = rp + bp0;
      float prob = 0.5f * tanhf(0.5f * z) + 0.5f;   // XLA logistic
      uint32_t bits = random_bits32(kp0, kp1, (unsigned long long)i);
      float u = u01_from_bits(bits);
      sgen[(warp << 2) + r] = (u < prob * anr[r]) ? 1 : 0;
      g_best[i] = 0ull;
    }
  }
  __syncthreads();
  if (tid < 2) {
    uint32_t w = 0;
#pragma unroll
    for (int k = 0; k < 32; k++) w |= (uint32_t)sgen[(tid << 5) + k] << k;
    g_gensmask[(blockIdx.x << 1) + tid] = w;
  }
}

// ---------- Kernel B: select — derives its candidate window from the bitmask ----------
__global__ void __launch_bounds__(SEL_THREADS) k_select(const float* __restrict__ nodes,
                                                        const float* __restrict__ active_nodes,
                                                        uint32_t ks0, uint32_t ks1) {
  __shared__ __align__(16) float sh[TILE_J * TILE_STRIDE];
  __shared__ __align__(16) float qsh[CAND_TILE * DD];
  __shared__ float s_qn[CAND_TILE];
  __shared__ int   s_ii[CAND_TILE];
  __shared__ int   s_glist[CAND_TILE];
  __shared__ int   s_wsum[8];
  const int tid = threadIdx.x;
  const int lane = tid & 31;
  const int wid = tid >> 5;
  const int jj = tid & 127;
  const int grp2 = tid >> 7;

  const uint32_t mw = g_gensmask[tid];
  const int cnt = __popc(mw);
  int incl = warp_incl_scan(cnt, lane);
  if (lane == 31) s_wsum[wid] = incl;
  __syncthreads();
  int wbase = 0, ncand = 0;
#pragma unroll
  for (int w = 0; w < 8; w++) {
    int v = s_wsum[w];
    if (w < wid) wbase += v;
    ncand += v;
  }
  const int mypre = wbase + incl - cnt;

  const int ng = (ncand + CAND_TILE - 1) / CAND_TILE;
  const int total = NCHUNK * ng;
  for (int w = blockIdx.x; w < total; w += gridDim.x) {
    const int chunk = w / ng;
    const int grp = w - chunk * ng;
    const int c0 = grp * CAND_TILE;
    const int jbase = chunk << 7;
    if (cnt) {
      uint32_t m = mw;
      int r = mypre;
      while (m) {
        int b = __ffs((int)m) - 1;
        if (r >= c0 && r < c0 + CAND_TILE) s_glist[r - c0] = (tid << 5) + b;
        m &= m - 1;
        r++;
      }
    }
    __syncthreads();
    {
      const float4* src = reinterpret_cast<const float4*>(nodes + (jbase << 6));
#pragma unroll
      for (int s = 0; s < 8; s++) {
        int idx4 = (s << 8) + tid;
        int row = idx4 >> 4, col4 = idx4 & 15;
        reinterpret_cast<float4*>(sh + row * TILE_STRIDE)[col4] = src[idx4];
      }
    }
    if (tid < CAND_TILE) {
      int idx = c0 + tid;
      int i = (idx < ncand) ? s_glist[tid] : 0;
      s_ii[tid] = i;
      s_qn[tid] = g_qn[i];
    }
#pragma unroll
    for (int s = 0; s < 2; s++) {
      int t4 = (s << 8) + tid;
      int c = t4 >> 4, k4 = t4 & 15;
      int idx = c0 + c;
      float4 qv = (idx < ncand)
          ? reinterpret_cast<const float4*>(g_queries + s_glist[c] * DD)[k4]
          : make_float4(0.f, 0.f, 0.f, 0.f);
      reinterpret_cast<float4*>(qsh + c * DD)[k4] = qv;
    }
    __syncthreads();
    const int j = jbase + jj;
    const float hn = g_hn[j];
    const float act = active_nodes[j];
    const float4* rowf4 = reinterpret_cast<const float4*>(sh + jj * TILE_STRIDE);
    const int clim = (ncand - c0 < CAND_TILE) ? (ncand - c0) : CAND_TILE;
    const int cbeg = grp2 << 4;
    const int cend = (cbeg + 16 < clim) ? cbeg + 16 : clim;
    for (int c = cbeg; c < cend; c++) {
      const int i = s_ii[c];
      const float4* qf4 = reinterpret_cast<const float4*>(qsh + c * DD);
      float ax = 0.f, ay = 0.f, az = 0.f, aw = 0.f;
#pragma unroll
      for (int kk = 0; kk < 16; kk++) {
        float4 r = rowf4[kk];
        float4 q = qf4[kk];
        ax = fmaf(q.x, r.x, ax);
        ay = fmaf(q.y, r.y, ay);
        az = fmaf(q.z, r.z, az);
        aw = fmaf(q.w, r.w, aw);
      }
      float num = (ax + az) + (ay + aw);
      float sc = num / (sqrtf(s_qn[c] * hn) + 1e-8f);
      sc = fminf(fmaxf(sc, -10000.f), 10000.f);
      if (act <= 0.f) sc = NEGV;
      if (j == i) sc = NEGV;
      unsigned long long lin = (unsigned long long)i * NN + (unsigned long long)j;
      uint32_t bits = random_bits32(ks0, ks1, lin);
      float u = fmaxf(TINYF, u01_from_bits(bits) + TINYF);
      float g = -logf(-logf(u));
      unsigned long long key = enc_key(sc + g, j);
#pragma unroll
      for (int d = 16; d > 0; d >>= 1) {
        unsigned long long o = __shfl_xor_sync(0xffffffffu, key, d);
        if (o > key) key = o;
      }
      if (lane == 0) atomicMax(&g_best[i], key);
    }
    __syncthreads();
  }
}

// ---- Kernel C: e_active + glist + exist-hash + compaction, ONE block ----
__global__ void __launch_bounds__(1024) k_cc(const float* __restrict__ active_edges,
                                             const int* __restrict__ senders,
                                             const int* __restrict__ receivers) {
  __shared__ unsigned long long hkey[HASH_SZ];
  __shared__ int   hcid[HASH_SZ];
  __shared__ float swF[32];
  __shared__ int   swA[32];
  __shared__ int   pre[33];
  const int tid = threadIdx.x;  // 1024
  const int lane = tid & 31, wid = tid >> 5;

  {
    const float4* ae4 = reinterpret_cast<const float4*>(active_edges);
    float s = 0.f;
#pragma unroll
    for (int r = 0; r < 4; r++) {
      float4 v = ae4[tid + (r << 10)];
      s += v.x + v.y + v.z + v.w;
    }
#pragma unroll
    for (int d = 16; d > 0; d >>= 1) s += __shfl_xor_sync(0xffffffffu, s, d);
    if (lane == 0) swF[wid] = s;
  }
  const uint32_t mw = (tid < NMASKW) ? g_gensmask[tid] : 0u;
  const int cnt = __popc(mw);
  int incl = warp_incl_scan(cnt, lane);
  if (lane == 31) swA[wid] = incl;
  __syncthreads();
  if (tid == 0) {
    pre[0] = 0;
#pragma unroll
    for (int w = 0; w < 32; w++) pre[w + 1] = pre[w] + swA[w];
    g_ncand = pre[32];
    float t = 0.f;
#pragma unroll
    for (int w = 0; w < 32; w++) t += swF[w];
    g_eactive = (int)t;
  }
  __syncthreads();
  const int ncand = pre[32];
  {
    int r = pre[wid] + incl - cnt;
    uint32_t m = mw;
    while (m) {
      int b = __ffs((int)m) - 1;
      g_glist[r] = (tid << 5) + b;
      g_flag[r] = 1;
      m &= m - 1;
      r++;
    }
  }
  __syncthreads();

  if (ncand <= HASH_CAP) {
#pragma unroll
    for (int r = 0; r < HASH_SZ / 1024; r++) hkey[tid + (r << 10)] = EMPTYK;
    __syncthreads();
    for (int c = tid; c < ncand; c += 1024) {
      int i = g_glist[c];
      unsigned long long b = g_best[i];
      uint32_t sel = 0xFFFFFFFFu - (uint32_t)(b & 0xFFFFFFFFull);
      unsigned long long key = ((unsigned long long)(uint32_t)i << 32) | sel;
      uint32_t h = (uint32_t)((key * 0x9E3779B97F4A7C15ull) >> 40) & (HASH_SZ - 1);
      while (true) {
        unsigned long long prev = atomicCAS(&hkey[h], EMPTYK, key);
        if (prev == EMPTYK) { hcid[h] = c; break; }
        h = (h + 1) & (HASH_SZ - 1);
      }
    }
    __syncthreads();
    const int4* s4 = reinterpret_cast<const int4*>(senders);
    const int4* r4 = reinterpret_cast<const int4*>(receivers);
#pragma unroll
    for (int r = 0; r < EE / 4 / 1024; r++) {
      int idx4 = tid + (r << 10);
      int4 sv = s4[idx4];
      int4 rv = r4[idx4];
      const int ss[4] = {sv.x, sv.y, sv.z, sv.w};
      const int rr[4] = {rv.x, rv.y, rv.z, rv.w};
#pragma unroll
      for (int q = 0; q < 4; q++) {
        unsigned long long key =
            ((unsigned long long)(uint32_t)ss[q] << 32) | (uint32_t)rr[q];
        uint32_t h = (uint32_t)((key * 0x9E3779B97F4A7C15ull) >> 40) & (HASH_SZ - 1);
        while (true) {
          unsigned long long k = hkey[h];
          if (k == EMPTYK) break;
          if (k == key) { g_flag[hcid[h]] = 0; break; }
          h = (h + 1) & (HASH_SZ - 1);
        }
      }
    }
    __syncthreads();
  } else {
    for (int c = tid; c < ncand; c += 1024) {
      int i = g_glist[c];
      unsigned long long b = g_best[i];
      uint32_t sel = 0xFFFFFFFFu - (uint32_t)(b & 0xFFFFFFFFull);
      int found = 0;
      for (int e = 0; e < EE; e++)
        found |= (senders[e] == i && (uint32_t)receivers[e] == sel);
      if (found) g_flag[c] = 0;
    }
    __syncthreads();
  }

  int flags[8];
  int ccnt = 0;
#pragma unroll
  for (int r = 0; r < 8; r++) {
    int c = tid * 8 + r;
    flags[r] = (c < ncand) ? g_flag[c] : 0;
    ccnt += flags[r];
  }
  int cincl = warp_incl_scan(ccnt, lane);
  if (lane == 31) swA[wid] = cincl;
  __syncthreads();
  if (tid == 0) {
    pre[0] = 0;
#pragma unroll
    for (int w = 0; w < 32; w++) pre[w + 1] = pre[w] + swA[w];
    int total = pre[32];
    int allowed = EE - g_eactive - 1;
    int n = total < 0 ? 0 : total;
    if (n > allowed) n = allowed;
    g_ngens = n;
  }
  __syncthreads();
  int off = pre[wid] + cincl - ccnt;
#pragma unroll
  for (int r = 0; r < 8; r++) {
    int c = tid * 8 + r;
    if (flags[r]) {
      int i = g_glist[c];
      unsigned long long b = g_best[i];
      g_newsend[off] = i;
      g_newrec[off] = (int)(0xFFFFFFFFu - (uint32_t)(b & 0xFFFFFFFFull));
      off++;
    }
  }
}

// ---------- Kernel D: output writer — 1 float4/thread, full occupancy ----------
// Layout: [ new_edges (E*D f32) | nsend (E) | nrec (E) | naedges (E) ]
__global__ void __launch_bounds__(256) k_out(const float* __restrict__ edges,
                                             const int* __restrict__ senders,
                                             const int* __restrict__ receivers,
                                             float4* __restrict__ out,
                                             uint32_t ke0, uint32_t ke1, int out_size) {
  const int idx4 = blockIdx.x * 256 + threadIdx.x;
  const int base = idx4 << 2;
  if (base >= out_size) return;
  const int ngen = g_ngens;
  const int ea = g_eactive;
  const int T1 = EE * DD;
  float4 v;
  if (base < T1) {
    v = reinterpret_cast<const float4*>(edges)[idx4];
    int e = base >> 6;
    if (e >= ea && e < ea + ngen) {
      float* vp = reinterpret_cast<float*>(&v);
#pragma unroll
      for (int cmp = 0; cmp < 4; cmp++) {
        uint32_t bits = random_bits32(ke0, ke1, (unsigned long long)(base + cmp));
        float u01 = u01_from_bits(bits);
        const float lo = -0.99999994f;
        float uu = fmaxf(lo, fmaf(u01, 2.0f, lo));
        vp[cmp] += 1.41421356f * xla_erfinv(uu);
      }
    }
  } else if (base < T1 + EE) {
    float* vp = reinterpret_cast<float*>(&v);
#pragma unroll
    for (int cmp = 0; cmp < 4; cmp++) {
      int j = base + cmp - T1;
      float x;
      if (j < ea)             x = (float)senders[j];
      else if (j < ea + ngen) x = (float)g_newsend[j - ea];
      else                    x = (float)(NN - 1);
      vp[cmp] = x;
    }
  } else if (base < T1 + 2 * EE) {
    float* vp = reinterpret_cast<float*>(&v);
#pragma unroll
    for (int cmp = 0; cmp < 4; cmp++) {
      int j = base + cmp - T1 - EE;
      float x;
      if (j < ea)             x = (float)receivers[j];
      else if (j < ea + ngen) x = (float)g_newrec[j - ea];
      else                    x = (float)(NN - 1);
      vp[cmp] = x;
    }
  } else {
    float* vp = reinterpret_cast<float*>(&v);
#pragma unroll
    for (int cmp = 0; cmp < 4; cmp++) {
      int j = base + cmp - T1 - 2 * EE;
      vp[cmp] = (j < ea + ngen && j >= 0) ? 1.0f : 0.0f;
    }
  }
  if (base + 4 <= out_size) {
    out[idx4] = v;
  } else {
    // partial tail (out_size % 4 != 0 — not expected)
    float* vp = reinterpret_cast<float*>(&v);
    float* os = reinterpret_cast<float*>(out);
    for (int cmp = 0; cmp < out_size - base; cmp++) os[base + cmp] = vp[cmp];
  }
}

// ---------------- host ----------------
extern "C" void kernel_launch(void* const* d_in, const int* in_sizes, int n_in,
                              void* d_out, int out_size) {
  const float* nodes        = (const float*)d_in[0];
  const float* edges        = (const float*)d_in[1];
  const int*   receivers    = (const int*)d_in[2];
  const int*   senders      = (const int*)d_in[3];
  const float* active_nodes = (const float*)d_in[4];
  const float* active_edges = (const float*)d_in[5];
  const float* Wq           = (const float*)d_in[6];
  const float* bq           = (const float*)d_in[7];
  const float* Wp           = (const float*)d_in[8];
  const float* bp           = (const float*)d_in[9];
  (void)in_sizes; (void)n_in;

  const uint32_t K0 = 0u, K1 = 42u;
  uint32_t kp0, kp1, ke0, ke1, ks0, ks1;
  threefry2x32(K0, K1, 0u, 0u, &kp0, &kp1);  // key_prob
  threefry2x32(K0, K1, 0u, 1u, &ke0, &ke1);  // key_edges
  threefry2x32(K0, K1, 0u, 2u, &ks0, &ks1);  // key_samp

  k_prep<<<NN / 64, 512>>>(nodes, Wq, bq, Wp, bp, active_nodes, kp0, kp1);
  k_select<<<592, SEL_THREADS>>>(nodes, active_nodes, ks0, ks1);
  k_cc<<<1, 1024>>>(active_edges, senders, receivers);

  int n4 = (out_size + 3) >> 2;
  int blocks = (n4 + 255) / 256;
  k_out<<<blocks, 256>>>(edges, senders, receivers, (float4*)d_out, ke0, ke1, out_size);
}